// round 1
// baseline (speedup 1.0000x reference)
#include <cuda_runtime.h>
#include <math.h>

#define BATCH 16
#define SEQ   1024
#define CDIM  768
#define NHEAD 12
#define HDIM  64
#define C3    (3*CDIM)
#define MTOT  (BATCH*SEQ)

// Scratch (allocation-free rule: __device__ globals)
__device__ float g_qkv[(size_t)MTOT * C3];   // [16384, 2304]
__device__ float g_y[(size_t)MTOT * CDIM];   // [16384, 768]

// ---------------------------------------------------------------------------
// GEMM: C[M,N] = A[M,K] @ B[K,N] + bias[N]   (row-major, all dims % 128 == 0,
// K % 8 == 0). 128x128 block tile, BK=8, 256 threads, 8x8 per-thread frag.
// ---------------------------------------------------------------------------
__global__ __launch_bounds__(256)
void gemm_bias_kernel(const float* __restrict__ A, const float* __restrict__ B,
                      const float* __restrict__ bias, float* __restrict__ C,
                      int M, int N, int K)
{
    const int BM = 128, BN = 128, BK = 8;
    __shared__ __align__(16) float As[BK][BM + 4];   // A tile, transposed
    __shared__ __align__(16) float Bs[BK][BN];

    const int tid = threadIdx.x;
    const int tx = tid & 15;          // 0..15  -> col frag
    const int ty = tid >> 4;          // 0..15  -> row frag
    const int bm = blockIdx.y * BM;
    const int bn = blockIdx.x * BN;

    const int arow = tid >> 1;        // 0..127
    const int acol = (tid & 1) * 4;   // 0 or 4
    const int brow = tid >> 5;        // 0..7
    const int bcol = (tid & 31) * 4;  // 0..124

    const float* Aptr = A + (size_t)(bm + arow) * K + acol;
    const float* Bptr = B + (size_t)brow * N + bn + bcol;

    float acc[8][8];
    #pragma unroll
    for (int i = 0; i < 8; i++)
        #pragma unroll
        for (int j = 0; j < 8; j++) acc[i][j] = 0.0f;

    for (int k0 = 0; k0 < K; k0 += BK) {
        float4 a4 = *(const float4*)(Aptr + k0);
        float4 b4 = *(const float4*)(Bptr + (size_t)k0 * N);
        As[acol + 0][arow] = a4.x;
        As[acol + 1][arow] = a4.y;
        As[acol + 2][arow] = a4.z;
        As[acol + 3][arow] = a4.w;
        *(float4*)&Bs[brow][bcol] = b4;
        __syncthreads();

        #pragma unroll
        for (int kk = 0; kk < BK; kk++) {
            float ar[8], br[8];
            *(float4*)&ar[0] = *(const float4*)&As[kk][ty * 8];
            *(float4*)&ar[4] = *(const float4*)&As[kk][ty * 8 + 4];
            *(float4*)&br[0] = *(const float4*)&Bs[kk][tx * 8];
            *(float4*)&br[4] = *(const float4*)&Bs[kk][tx * 8 + 4];
            #pragma unroll
            for (int i = 0; i < 8; i++)
                #pragma unroll
                for (int j = 0; j < 8; j++)
                    acc[i][j] += ar[i] * br[j];
        }
        __syncthreads();
    }

    float bv[8];
    *(float4*)&bv[0] = *(const float4*)&bias[bn + tx * 8];
    *(float4*)&bv[4] = *(const float4*)&bias[bn + tx * 8 + 4];

    #pragma unroll
    for (int i = 0; i < 8; i++) {
        float* crow = C + (size_t)(bm + ty * 8 + i) * N + bn + tx * 8;
        float4 o0 = make_float4(acc[i][0] + bv[0], acc[i][1] + bv[1],
                                acc[i][2] + bv[2], acc[i][3] + bv[3]);
        float4 o1 = make_float4(acc[i][4] + bv[4], acc[i][5] + bv[5],
                                acc[i][6] + bv[6], acc[i][7] + bv[7]);
        *(float4*)crow = o0;
        *(float4*)(crow + 4) = o1;
    }
}

// ---------------------------------------------------------------------------
// Flash-style causal attention, fp32.
// Grid: (qt = T/64, b*h). Block: 128 threads.
// Thread t: col group g = t%8 (8 cols: g*8..g*8+7), row group p = t/8
// (4 rows: 4p..4p+3). Per 64x64 S tile the 8 g-threads of a row group are
// consecutive lanes -> shfl_xor 1/2/4 row reductions.
// Smem: Qst/Kst transposed [kk][row] with pad 68 (float4-aligned, no bank
// conflicts), Vs row-major [j][c], Ps [row][j].
// ---------------------------------------------------------------------------
#define PAD 68
#define ATTN_SMEM (4 * 64 * PAD * (int)sizeof(float))   // 69632 B

__global__ __launch_bounds__(128)
void attn_kernel(const float* __restrict__ qkv, float* __restrict__ y)
{
    extern __shared__ float sm[];
    float* Qst = sm;                 // [64 kk][64 row] (pad)
    float* Kst = sm + 64 * PAD;      // [64 kk][64 col]
    float* Vs  = sm + 2 * 64 * PAD;  // [64 j ][64 c  ]
    float* Ps  = sm + 3 * 64 * PAD;  // [64 r ][64 j  ]

    const int tid = threadIdx.x;
    const int g = tid & 7;
    const int p = tid >> 3;
    const int qt = blockIdx.x;
    const int bh = blockIdx.y;
    const int b = bh / NHEAD;
    const int h = bh % NHEAD;
    const float scale = 0.125f;      // 1/sqrt(64)
    const float NEG = -1e30f;

    const float* qbase = qkv + ((size_t)(b * SEQ) + qt * 64) * C3 + h * HDIM;
    const float* kbase = qkv + (size_t)(b * SEQ) * C3 + CDIM + h * HDIM;
    const float* vbase = qkv + (size_t)(b * SEQ) * C3 + 2 * CDIM + h * HDIM;

    // Load Q tile transposed: Qst[c][row]
    for (int i = tid; i < 64 * 16; i += 128) {
        int row = i >> 4;
        int c4  = (i & 15) << 2;
        float4 v = *(const float4*)(qbase + (size_t)row * C3 + c4);
        Qst[(c4 + 0) * PAD + row] = v.x;
        Qst[(c4 + 1) * PAD + row] = v.y;
        Qst[(c4 + 2) * PAD + row] = v.z;
        Qst[(c4 + 3) * PAD + row] = v.w;
    }

    float m[4], l[4], o[4][8];
    #pragma unroll
    for (int i = 0; i < 4; i++) {
        m[i] = NEG; l[i] = 0.0f;
        #pragma unroll
        for (int j = 0; j < 8; j++) o[i][j] = 0.0f;
    }
    __syncthreads();

    for (int kt = 0; kt <= qt; kt++) {
        // Load K (transposed) and V tiles
        const float* kb = kbase + (size_t)(kt * 64) * C3;
        const float* vb = vbase + (size_t)(kt * 64) * C3;
        for (int i = tid; i < 64 * 16; i += 128) {
            int row = i >> 4;
            int c4  = (i & 15) << 2;
            float4 kv = *(const float4*)(kb + (size_t)row * C3 + c4);
            Kst[(c4 + 0) * PAD + row] = kv.x;
            Kst[(c4 + 1) * PAD + row] = kv.y;
            Kst[(c4 + 2) * PAD + row] = kv.z;
            Kst[(c4 + 3) * PAD + row] = kv.w;
            *(float4*)&Vs[row * PAD + c4] =
                *(const float4*)(vb + (size_t)row * C3 + c4);
        }
        __syncthreads();

        // S = (Q K^T) * scale
        float s[4][8];
        #pragma unroll
        for (int i = 0; i < 4; i++)
            #pragma unroll
            for (int j = 0; j < 8; j++) s[i][j] = 0.0f;

        #pragma unroll 4
        for (int kk = 0; kk < 64; kk++) {
            float4 q4 = *(const float4*)&Qst[kk * PAD + p * 4];
            float qa[4] = {q4.x, q4.y, q4.z, q4.w};
            float kv[8];
            *(float4*)&kv[0] = *(const float4*)&Kst[kk * PAD + g * 8];
            *(float4*)&kv[4] = *(const float4*)&Kst[kk * PAD + g * 8 + 4];
            #pragma unroll
            for (int i = 0; i < 4; i++)
                #pragma unroll
                for (int j = 0; j < 8; j++)
                    s[i][j] += qa[i] * kv[j];
        }

        const bool diag = (kt == qt);

        #pragma unroll
        for (int i = 0; i < 4; i++) {
            const int row = p * 4 + i;
            float mloc = NEG;
            #pragma unroll
            for (int j = 0; j < 8; j++) {
                float sv = s[i][j] * scale;
                if (diag && (g * 8 + j) > row) sv = NEG;
                s[i][j] = sv;
                mloc = fmaxf(mloc, sv);
            }
            mloc = fmaxf(mloc, __shfl_xor_sync(0xffffffffu, mloc, 1));
            mloc = fmaxf(mloc, __shfl_xor_sync(0xffffffffu, mloc, 2));
            mloc = fmaxf(mloc, __shfl_xor_sync(0xffffffffu, mloc, 4));
            float mnew = fmaxf(m[i], mloc);
            float alpha = __expf(m[i] - mnew);
            float lloc = 0.0f;
            #pragma unroll
            for (int j = 0; j < 8; j++) {
                float pv = __expf(s[i][j] - mnew);
                s[i][j] = pv;
                lloc += pv;
            }
            lloc += __shfl_xor_sync(0xffffffffu, lloc, 1);
            lloc += __shfl_xor_sync(0xffffffffu, lloc, 2);
            lloc += __shfl_xor_sync(0xffffffffu, lloc, 4);
            l[i] = l[i] * alpha + lloc;
            m[i] = mnew;
            #pragma unroll
            for (int j = 0; j < 8; j++) o[i][j] *= alpha;
            *(float4*)&Ps[row * PAD + g * 8] =
                make_float4(s[i][0], s[i][1], s[i][2], s[i][3]);
            *(float4*)&Ps[row * PAD + g * 8 + 4] =
                make_float4(s[i][4], s[i][5], s[i][6], s[i][7]);
        }
        __syncwarp();

        // O += P @ V
        #pragma unroll 4
        for (int j = 0; j < 64; j++) {
            float vv[8];
            *(float4*)&vv[0] = *(const float4*)&Vs[j * PAD + g * 8];
            *(float4*)&vv[4] = *(const float4*)&Vs[j * PAD + g * 8 + 4];
            #pragma unroll
            for (int i = 0; i < 4; i++) {
                float pp = Ps[(p * 4 + i) * PAD + j];
                #pragma unroll
                for (int jj = 0; jj < 8; jj++)
                    o[i][jj] += pp * vv[jj];
            }
        }
        __syncthreads();
    }

    // Epilogue: normalize, write to y in [B,T,C] layout
    #pragma unroll
    for (int i = 0; i < 4; i++) {
        const int row = p * 4 + i;
        float inv = 1.0f / l[i];
        float* yb = y + ((size_t)(b * SEQ) + qt * 64 + row) * CDIM + h * HDIM + g * 8;
        float4 o0 = make_float4(o[i][0] * inv, o[i][1] * inv,
                                o[i][2] * inv, o[i][3] * inv);
        float4 o1 = make_float4(o[i][4] * inv, o[i][5] * inv,
                                o[i][6] * inv, o[i][7] * inv);
        *(float4*)yb = o0;
        *(float4*)(yb + 4) = o1;
    }
}

// ---------------------------------------------------------------------------
extern "C" void kernel_launch(void* const* d_in, const int* in_sizes, int n_in,
                              void* d_out, int out_size)
{
    const float* x      = (const float*)d_in[0];
    const float* W_attn = (const float*)d_in[1];
    const float* b_attn = (const float*)d_in[2];
    const float* W_proj = (const float*)d_in[3];
    const float* b_proj = (const float*)d_in[4];
    float* out = (float*)d_out;

    float* qkvp = nullptr;
    float* yp   = nullptr;
    cudaGetSymbolAddress((void**)&qkvp, g_qkv);
    cudaGetSymbolAddress((void**)&yp, g_y);

    // 1) QKV projection: [16384,768] @ [768,2304] + b
    {
        dim3 grid(3 * CDIM / 128, MTOT / 128);   // (18, 128)
        gemm_bias_kernel<<<grid, 256>>>(x, W_attn, b_attn, qkvp,
                                        MTOT, 3 * CDIM, CDIM);
    }

    // 2) Causal flash attention
    {
        cudaFuncSetAttribute(attn_kernel,
                             cudaFuncAttributeMaxDynamicSharedMemorySize,
                             ATTN_SMEM);
        dim3 grid(SEQ / 64, BATCH * NHEAD);      // (16, 192)
        attn_kernel<<<grid, 128, ATTN_SMEM>>>(qkvp, yp);
    }

    // 3) Output projection: [16384,768] @ [768,768] + b
    {
        dim3 grid(CDIM / 128, MTOT / 128);       // (6, 128)
        gemm_bias_kernel<<<grid, 256>>>(yp, W_proj, b_proj, out,
                                        MTOT, CDIM, CDIM);
    }
}

// round 3
// speedup vs baseline: 1.6037x; 1.6037x over previous
#include <cuda_runtime.h>
#include <cstdint>
#include <math.h>

#define BATCH 16
#define SEQ   1024
#define CDIM  768
#define NHEAD 12
#define HDIM  64
#define C3    (3*CDIM)
#define MTOT  (BATCH*SEQ)

// Scratch (allocation-free rule: __device__ globals)
__device__ float g_qkv[(size_t)MTOT * C3];   // [16384, 2304]
__device__ float g_y[(size_t)MTOT * CDIM];   // [16384, 768]

// ============================================================================
// Baseline-PTX helpers (no sm_103a-only features!)
// ============================================================================
__device__ __forceinline__ uint32_t smem_u32(const void* p) {
    uint32_t a;
    asm("{ .reg .u64 t; cvta.to.shared.u64 t, %1; cvt.u32.u64 %0, t; }"
        : "=r"(a) : "l"(p));
    return a;
}
__device__ __forceinline__ uint32_t f2tf32(float x) {
    uint32_t y;
    asm("cvt.rna.tf32.f32 %0, %1;" : "=r"(y) : "f"(x));
    return y;
}
__device__ __forceinline__ void cp_async16(uint32_t dst, const void* src) {
    asm volatile("cp.async.cg.shared.global [%0], [%1], 16;"
                 :: "r"(dst), "l"(src));
}
#define CP_COMMIT() asm volatile("cp.async.commit_group;" ::: "memory")
#define CP_WAIT(n)  asm volatile("cp.async.wait_group %0;" :: "n"(n) : "memory")

__device__ __forceinline__ void mma_tf32(float* d, const uint32_t* a,
                                         const uint32_t* b) {
    asm volatile(
        "mma.sync.aligned.m16n8k8.row.col.f32.tf32.tf32.f32 "
        "{%0,%1,%2,%3}, {%4,%5,%6,%7}, {%8,%9}, {%0,%1,%2,%3};"
        : "+f"(d[0]), "+f"(d[1]), "+f"(d[2]), "+f"(d[3])
        : "r"(a[0]), "r"(a[1]), "r"(a[2]), "r"(a[3]),
          "r"(b[0]), "r"(b[1]));
}

// ============================================================================
// tf32 mma.sync GEMM: C[M,N] = A[M,K] @ B[K,N] + bias[N]
// CTA tile 128x128, BK=32, 256 threads, warp tile 64x32 (warp grid 2x4).
// A smem stride 36 (conflict-free A-frag LDS), B smem stride 136.
// Double-buffered cp.async pipeline.
// ============================================================================
#define AS_STRIDE 36
#define BS_STRIDE 136
#define AS_ELEMS  (128 * AS_STRIDE)     // 4608 floats
#define BS_ELEMS  (32 * BS_STRIDE)      // 4352 floats
#define GEMM_SMEM ((2 * (AS_ELEMS + BS_ELEMS)) * (int)sizeof(float))  // 71680

__global__ __launch_bounds__(256)
void gemm_mma_kernel(const float* __restrict__ A, const float* __restrict__ B,
                     const float* __restrict__ bias, float* __restrict__ C,
                     int K, int N)
{
    extern __shared__ float smem[];
    float* Asm[2] = { smem, smem + AS_ELEMS };
    float* Bsm[2] = { smem + 2 * AS_ELEMS, smem + 2 * AS_ELEMS + BS_ELEMS };

    const int tid  = threadIdx.x;
    const int wid  = tid >> 5;
    const int lane = tid & 31;
    const int bm = blockIdx.y * 128;
    const int bn = blockIdx.x * 128;

    const int warp_m = (wid & 1) * 64;   // 0 or 64
    const int warp_n = (wid >> 1) * 32;  // 0,32,64,96

    // cp.async tile loaders --------------------------------------------------
    // A tile: 128 rows x 32 floats = 1024 float4 chunks; 4 per thread.
    // B tile: 32 rows x 128 floats = 1024 float4 chunks; 4 per thread.
    const int a_row0 = tid >> 1;            // with i stride: rows tid>>1 + 128? no:
    // chunk = tid + 256*i  -> row = chunk>>3, c4 = chunk&7
    // b chunk -> row = chunk>>5, c4 = chunk&31

    auto load_tile = [&](int buf, int it) {
        const int koff = it * 32;
        const uint32_t asb = smem_u32(Asm[buf]);
        const uint32_t bsb = smem_u32(Bsm[buf]);
        #pragma unroll
        for (int i = 0; i < 4; ++i) {
            int chunk = tid + 256 * i;
            int ar = chunk >> 3, ac4 = chunk & 7;
            cp_async16(asb + (uint32_t)(ar * AS_STRIDE + ac4 * 4) * 4,
                       A + (size_t)(bm + ar) * K + koff + ac4 * 4);
            int br = chunk >> 5, bc4 = chunk & 31;
            cp_async16(bsb + (uint32_t)(br * BS_STRIDE + bc4 * 4) * 4,
                       B + (size_t)(koff + br) * N + bn + bc4 * 4);
        }
    };
    (void)a_row0;

    float acc[4][4][4];
    #pragma unroll
    for (int mi = 0; mi < 4; mi++)
        #pragma unroll
        for (int ni = 0; ni < 4; ni++)
            #pragma unroll
            for (int q = 0; q < 4; q++) acc[mi][ni][q] = 0.0f;

    const int nk = K / 32;
    load_tile(0, 0);
    CP_COMMIT();

    for (int it = 0; it < nk; ++it) {
        if (it + 1 < nk) {
            load_tile((it + 1) & 1, it + 1);
            CP_COMMIT();
            CP_WAIT(1);
        } else {
            CP_WAIT(0);
        }
        __syncthreads();

        const float* as = Asm[it & 1];
        const float* bs = Bsm[it & 1];
        const int lr = lane >> 2;   // 0..7
        const int lc = lane & 3;    // 0..3

        #pragma unroll
        for (int ks = 0; ks < 4; ks++) {
            const int k0 = ks * 8;
            uint32_t af[4][4];
            #pragma unroll
            for (int mi = 0; mi < 4; mi++) {
                const int r = warp_m + mi * 16 + lr;
                af[mi][0] = f2tf32(as[r * AS_STRIDE + k0 + lc]);
                af[mi][1] = f2tf32(as[(r + 8) * AS_STRIDE + k0 + lc]);
                af[mi][2] = f2tf32(as[r * AS_STRIDE + k0 + 4 + lc]);
                af[mi][3] = f2tf32(as[(r + 8) * AS_STRIDE + k0 + 4 + lc]);
            }
            uint32_t bf[4][2];
            #pragma unroll
            for (int ni = 0; ni < 4; ni++) {
                const int c = warp_n + ni * 8 + lr;
                bf[ni][0] = f2tf32(bs[(k0 + lc) * BS_STRIDE + c]);
                bf[ni][1] = f2tf32(bs[(k0 + 4 + lc) * BS_STRIDE + c]);
            }
            #pragma unroll
            for (int mi = 0; mi < 4; mi++)
                #pragma unroll
                for (int ni = 0; ni < 4; ni++)
                    mma_tf32(acc[mi][ni], af[mi], bf[ni]);
        }
        __syncthreads();
    }

    // Epilogue: += bias, write float2 pairs
    const int lr = lane >> 2;
    const int lc2 = (lane & 3) * 2;
    #pragma unroll
    for (int ni = 0; ni < 4; ni++) {
        const int col = bn + warp_n + ni * 8 + lc2;
        const float2 bv = *(const float2*)(bias + col);
        #pragma unroll
        for (int mi = 0; mi < 4; mi++) {
            const int row0 = bm + warp_m + mi * 16 + lr;
            float2 o0 = make_float2(acc[mi][ni][0] + bv.x,
                                    acc[mi][ni][1] + bv.y);
            float2 o1 = make_float2(acc[mi][ni][2] + bv.x,
                                    acc[mi][ni][3] + bv.y);
            *(float2*)(C + (size_t)row0 * N + col) = o0;
            *(float2*)(C + (size_t)(row0 + 8) * N + col) = o1;
        }
    }
}

// ============================================================================
// Flash-style causal attention, fp32 (unchanged, known-good).
// ============================================================================
#define PAD 68
#define ATTN_SMEM (4 * 64 * PAD * (int)sizeof(float))

__global__ __launch_bounds__(128)
void attn_kernel(const float* __restrict__ qkv, float* __restrict__ y)
{
    extern __shared__ float sm[];
    float* Qst = sm;
    float* Kst = sm + 64 * PAD;
    float* Vs  = sm + 2 * 64 * PAD;
    float* Ps  = sm + 3 * 64 * PAD;

    const int tid = threadIdx.x;
    const int g = tid & 7;
    const int p = tid >> 3;
    const int qt = blockIdx.x;
    const int bh = blockIdx.y;
    const int b = bh / NHEAD;
    const int h = bh % NHEAD;
    const float scale = 0.125f;
    const float NEG = -1e30f;

    const float* qbase = qkv + ((size_t)(b * SEQ) + qt * 64) * C3 + h * HDIM;
    const float* kbase = qkv + (size_t)(b * SEQ) * C3 + CDIM + h * HDIM;
    const float* vbase = qkv + (size_t)(b * SEQ) * C3 + 2 * CDIM + h * HDIM;

    for (int i = tid; i < 64 * 16; i += 128) {
        int row = i >> 4;
        int c4  = (i & 15) << 2;
        float4 v = *(const float4*)(qbase + (size_t)row * C3 + c4);
        Qst[(c4 + 0) * PAD + row] = v.x;
        Qst[(c4 + 1) * PAD + row] = v.y;
        Qst[(c4 + 2) * PAD + row] = v.z;
        Qst[(c4 + 3) * PAD + row] = v.w;
    }

    float m[4], l[4], o[4][8];
    #pragma unroll
    for (int i = 0; i < 4; i++) {
        m[i] = NEG; l[i] = 0.0f;
        #pragma unroll
        for (int j = 0; j < 8; j++) o[i][j] = 0.0f;
    }
    __syncthreads();

    for (int kt = 0; kt <= qt; kt++) {
        const float* kb = kbase + (size_t)(kt * 64) * C3;
        const float* vb = vbase + (size_t)(kt * 64) * C3;
        for (int i = tid; i < 64 * 16; i += 128) {
            int row = i >> 4;
            int c4  = (i & 15) << 2;
            float4 kv = *(const float4*)(kb + (size_t)row * C3 + c4);
            Kst[(c4 + 0) * PAD + row] = kv.x;
            Kst[(c4 + 1) * PAD + row] = kv.y;
            Kst[(c4 + 2) * PAD + row] = kv.z;
            Kst[(c4 + 3) * PAD + row] = kv.w;
            *(float4*)&Vs[row * PAD + c4] =
                *(const float4*)(vb + (size_t)row * C3 + c4);
        }
        __syncthreads();

        float s[4][8];
        #pragma unroll
        for (int i = 0; i < 4; i++)
            #pragma unroll
            for (int j = 0; j < 8; j++) s[i][j] = 0.0f;

        #pragma unroll 4
        for (int kk = 0; kk < 64; kk++) {
            float4 q4 = *(const float4*)&Qst[kk * PAD + p * 4];
            float qa[4] = {q4.x, q4.y, q4.z, q4.w};
            float kv[8];
            *(float4*)&kv[0] = *(const float4*)&Kst[kk * PAD + g * 8];
            *(float4*)&kv[4] = *(const float4*)&Kst[kk * PAD + g * 8 + 4];
            #pragma unroll
            for (int i = 0; i < 4; i++)
                #pragma unroll
                for (int j = 0; j < 8; j++)
                    s[i][j] += qa[i] * kv[j];
        }

        const bool diag = (kt == qt);

        #pragma unroll
        for (int i = 0; i < 4; i++) {
            const int row = p * 4 + i;
            float mloc = NEG;
            #pragma unroll
            for (int j = 0; j < 8; j++) {
                float sv = s[i][j] * scale;
                if (diag && (g * 8 + j) > row) sv = NEG;
                s[i][j] = sv;
                mloc = fmaxf(mloc, sv);
            }
            mloc = fmaxf(mloc, __shfl_xor_sync(0xffffffffu, mloc, 1));
            mloc = fmaxf(mloc, __shfl_xor_sync(0xffffffffu, mloc, 2));
            mloc = fmaxf(mloc, __shfl_xor_sync(0xffffffffu, mloc, 4));
            float mnew = fmaxf(m[i], mloc);
            float alpha = __expf(m[i] - mnew);
            float lloc = 0.0f;
            #pragma unroll
            for (int j = 0; j < 8; j++) {
                float pv = __expf(s[i][j] - mnew);
                s[i][j] = pv;
                lloc += pv;
            }
            lloc += __shfl_xor_sync(0xffffffffu, lloc, 1);
            lloc += __shfl_xor_sync(0xffffffffu, lloc, 2);
            lloc += __shfl_xor_sync(0xffffffffu, lloc, 4);
            l[i] = l[i] * alpha + lloc;
            m[i] = mnew;
            #pragma unroll
            for (int j = 0; j < 8; j++) o[i][j] *= alpha;
            *(float4*)&Ps[row * PAD + g * 8] =
                make_float4(s[i][0], s[i][1], s[i][2], s[i][3]);
            *(float4*)&Ps[row * PAD + g * 8 + 4] =
                make_float4(s[i][4], s[i][5], s[i][6], s[i][7]);
        }
        __syncwarp();

        #pragma unroll 4
        for (int j = 0; j < 64; j++) {
            float vv[8];
            *(float4*)&vv[0] = *(const float4*)&Vs[j * PAD + g * 8];
            *(float4*)&vv[4] = *(const float4*)&Vs[j * PAD + g * 8 + 4];
            #pragma unroll
            for (int i = 0; i < 4; i++) {
                float pp = Ps[(p * 4 + i) * PAD + j];
                #pragma unroll
                for (int jj = 0; jj < 8; jj++)
                    o[i][jj] += pp * vv[jj];
            }
        }
        __syncthreads();
    }

    #pragma unroll
    for (int i = 0; i < 4; i++) {
        const int row = p * 4 + i;
        float inv = 1.0f / l[i];
        float* yb = y + ((size_t)(b * SEQ) + qt * 64 + row) * CDIM + h * HDIM + g * 8;
        float4 o0 = make_float4(o[i][0] * inv, o[i][1] * inv,
                                o[i][2] * inv, o[i][3] * inv);
        float4 o1 = make_float4(o[i][4] * inv, o[i][5] * inv,
                                o[i][6] * inv, o[i][7] * inv);
        *(float4*)yb = o0;
        *(float4*)(yb + 4) = o1;
    }
}

// ---------------------------------------------------------------------------
extern "C" void kernel_launch(void* const* d_in, const int* in_sizes, int n_in,
                              void* d_out, int out_size)
{
    const float* x      = (const float*)d_in[0];
    const float* W_attn = (const float*)d_in[1];
    const float* b_attn = (const float*)d_in[2];
    const float* W_proj = (const float*)d_in[3];
    const float* b_proj = (const float*)d_in[4];
    float* out = (float*)d_out;

    float *qkvp = nullptr, *yp = nullptr;
    cudaGetSymbolAddress((void**)&qkvp, g_qkv);
    cudaGetSymbolAddress((void**)&yp, g_y);

    // 1) QKV projection (tf32 mma.sync): [16384,768] @ [768,2304] + b
    {
        cudaFuncSetAttribute(gemm_mma_kernel,
                             cudaFuncAttributeMaxDynamicSharedMemorySize,
                             GEMM_SMEM);
        dim3 grid(C3 / 128, MTOT / 128);   // (18, 128)
        gemm_mma_kernel<<<grid, 256, GEMM_SMEM>>>(x, W_attn, b_attn, qkvp,
                                                  CDIM, C3);
    }

    // 2) Causal flash attention (fp32)
    {
        cudaFuncSetAttribute(attn_kernel,
                             cudaFuncAttributeMaxDynamicSharedMemorySize,
                             ATTN_SMEM);
        dim3 grid(SEQ / 64, BATCH * NHEAD);
        attn_kernel<<<grid, 128, ATTN_SMEM>>>(qkvp, yp);
    }

    // 3) Output projection (tf32 mma.sync): [16384,768] @ [768,768] + b
    {
        dim3 grid(CDIM / 128, MTOT / 128); // (6, 128)
        gemm_mma_kernel<<<grid, 256, GEMM_SMEM>>>(yp, W_proj, b_proj, out,
                                                  CDIM, CDIM);
    }
}

// round 4
// speedup vs baseline: 3.2953x; 2.0548x over previous
#include <cuda_runtime.h>
#include <cstdint>
#include <math.h>

#define BATCH 16
#define SEQ   1024
#define CDIM  768
#define NHEAD 12
#define HDIM  64
#define C3    (3*CDIM)
#define MTOT  (BATCH*SEQ)

// Scratch (allocation-free rule: __device__ globals)
__device__ float g_qkv[(size_t)MTOT * C3];     // [16384, 2304] tf32-rounded
__device__ float g_y[(size_t)MTOT * CDIM];     // [16384, 768]  tf32-rounded
__device__ float g_xt[(size_t)MTOT * CDIM];    // x  tf32-rounded
__device__ float g_wa[(size_t)CDIM * C3];      // W_attn tf32-rounded
__device__ float g_wp[(size_t)CDIM * CDIM];    // W_proj tf32-rounded

// ============================================================================
// Baseline-PTX helpers (no sm_103a-only features)
// ============================================================================
__device__ __forceinline__ uint32_t smem_u32(const void* p) {
    uint32_t a;
    asm("{ .reg .u64 t; cvta.to.shared.u64 t, %1; cvt.u32.u64 %0, t; }"
        : "=r"(a) : "l"(p));
    return a;
}
__device__ __forceinline__ uint32_t f2tf32(float x) {
    uint32_t y;
    asm("cvt.rna.tf32.f32 %0, %1;" : "=r"(y) : "f"(x));
    return y;
}
__device__ __forceinline__ float round_tf32(float x) {
    return __uint_as_float(f2tf32(x));
}
__device__ __forceinline__ void cp_async16(uint32_t dst, const void* src) {
    asm volatile("cp.async.cg.shared.global [%0], [%1], 16;"
                 :: "r"(dst), "l"(src));
}
#define CP_COMMIT() asm volatile("cp.async.commit_group;" ::: "memory")
#define CP_WAIT(n)  asm volatile("cp.async.wait_group %0;" :: "n"(n) : "memory")

__device__ __forceinline__ void mma_tf32(float* d, const uint32_t* a,
                                         const uint32_t* b) {
    asm volatile(
        "mma.sync.aligned.m16n8k8.row.col.f32.tf32.tf32.f32 "
        "{%0,%1,%2,%3}, {%4,%5,%6,%7}, {%8,%9}, {%0,%1,%2,%3};"
        : "+f"(d[0]), "+f"(d[1]), "+f"(d[2]), "+f"(d[3])
        : "r"(a[0]), "r"(a[1]), "r"(a[2]), "r"(a[3]),
          "r"(b[0]), "r"(b[1]));
}

// ============================================================================
// Elementwise tf32 pre-round (n % 4 == 0)
// ============================================================================
__global__ void round_kernel(const float* __restrict__ in,
                             float* __restrict__ out, int n)
{
    int i = (blockIdx.x * 256 + threadIdx.x) * 4;
    if (i < n) {
        float4 v = *(const float4*)(in + i);
        v.x = round_tf32(v.x); v.y = round_tf32(v.y);
        v.z = round_tf32(v.z); v.w = round_tf32(v.w);
        *(float4*)(out + i) = v;
    }
}

// ============================================================================
// tf32 mma.sync GEMM: C[M,N] = A[M,K] @ B[K,N] + bias[N]
// A,B pre-rounded to tf32. CTA tile 128x128, BK=32, 256 threads,
// warp tile 64x32. Double-buffered cp.async.
// ============================================================================
#define AS_STRIDE 36
#define BS_STRIDE 136
#define AS_ELEMS  (128 * AS_STRIDE)
#define BS_ELEMS  (32 * BS_STRIDE)
#define GEMM_SMEM ((2 * (AS_ELEMS + BS_ELEMS)) * (int)sizeof(float))  // 71680

template<bool ROUND_OUT>
__global__ __launch_bounds__(256, 2)
void gemm_mma_kernel(const float* __restrict__ A, const float* __restrict__ B,
                     const float* __restrict__ bias, float* __restrict__ C,
                     int K, int N)
{
    extern __shared__ float smem[];
    float* Asm[2] = { smem, smem + AS_ELEMS };
    float* Bsm[2] = { smem + 2 * AS_ELEMS, smem + 2 * AS_ELEMS + BS_ELEMS };

    const int tid  = threadIdx.x;
    const int wid  = tid >> 5;
    const int lane = tid & 31;
    const int bm = blockIdx.y * 128;
    const int bn = blockIdx.x * 128;
    const int warp_m = (wid & 1) * 64;
    const int warp_n = (wid >> 1) * 32;

    auto load_tile = [&](int buf, int it) {
        const int koff = it * 32;
        const uint32_t asb = smem_u32(Asm[buf]);
        const uint32_t bsb = smem_u32(Bsm[buf]);
        #pragma unroll
        for (int i = 0; i < 4; ++i) {
            int chunk = tid + 256 * i;
            int ar = chunk >> 3, ac4 = chunk & 7;
            cp_async16(asb + (uint32_t)(ar * AS_STRIDE + ac4 * 4) * 4,
                       A + (size_t)(bm + ar) * K + koff + ac4 * 4);
            int br = chunk >> 5, bc4 = chunk & 31;
            cp_async16(bsb + (uint32_t)(br * BS_STRIDE + bc4 * 4) * 4,
                       B + (size_t)(koff + br) * N + bn + bc4 * 4);
        }
    };

    float acc[4][4][4];
    #pragma unroll
    for (int mi = 0; mi < 4; mi++)
        #pragma unroll
        for (int ni = 0; ni < 4; ni++)
            #pragma unroll
            for (int q = 0; q < 4; q++) acc[mi][ni][q] = 0.0f;

    const int nk = K / 32;
    load_tile(0, 0);
    CP_COMMIT();

    for (int it = 0; it < nk; ++it) {
        if (it + 1 < nk) {
            load_tile((it + 1) & 1, it + 1);
            CP_COMMIT();
            CP_WAIT(1);
        } else {
            CP_WAIT(0);
        }
        __syncthreads();

        const float* as = Asm[it & 1];
        const float* bs = Bsm[it & 1];
        const int lr = lane >> 2;
        const int lc = lane & 3;

        #pragma unroll
        for (int ks = 0; ks < 4; ks++) {
            const int k0 = ks * 8;
            uint32_t af[4][4];
            #pragma unroll
            for (int mi = 0; mi < 4; mi++) {
                const int r = warp_m + mi * 16 + lr;
                af[mi][0] = __float_as_uint(as[r * AS_STRIDE + k0 + lc]);
                af[mi][1] = __float_as_uint(as[(r + 8) * AS_STRIDE + k0 + lc]);
                af[mi][2] = __float_as_uint(as[r * AS_STRIDE + k0 + 4 + lc]);
                af[mi][3] = __float_as_uint(as[(r + 8) * AS_STRIDE + k0 + 4 + lc]);
            }
            uint32_t bf[4][2];
            #pragma unroll
            for (int ni = 0; ni < 4; ni++) {
                const int c = warp_n + ni * 8 + lr;
                bf[ni][0] = __float_as_uint(bs[(k0 + lc) * BS_STRIDE + c]);
                bf[ni][1] = __float_as_uint(bs[(k0 + 4 + lc) * BS_STRIDE + c]);
            }
            #pragma unroll
            for (int mi = 0; mi < 4; mi++)
                #pragma unroll
                for (int ni = 0; ni < 4; ni++)
                    mma_tf32(acc[mi][ni], af[mi], bf[ni]);
        }
        __syncthreads();
    }

    const int lr = lane >> 2;
    const int lc2 = (lane & 3) * 2;
    #pragma unroll
    for (int ni = 0; ni < 4; ni++) {
        const int col = bn + warp_n + ni * 8 + lc2;
        const float2 bv = *(const float2*)(bias + col);
        #pragma unroll
        for (int mi = 0; mi < 4; mi++) {
            const int row0 = bm + warp_m + mi * 16 + lr;
            float v00 = acc[mi][ni][0] + bv.x, v01 = acc[mi][ni][1] + bv.y;
            float v10 = acc[mi][ni][2] + bv.x, v11 = acc[mi][ni][3] + bv.y;
            if (ROUND_OUT) {
                v00 = round_tf32(v00); v01 = round_tf32(v01);
                v10 = round_tf32(v10); v11 = round_tf32(v11);
            }
            *(float2*)(C + (size_t)row0 * N + col) = make_float2(v00, v01);
            *(float2*)(C + (size_t)(row0 + 8) * N + col) = make_float2(v10, v11);
        }
    }
}

// ============================================================================
// Flash attention with tf32 mma.sync.
// Block: 256 threads (8 warps), 128 q-rows (warp w owns rows w*16..w*16+15).
// kt tiles of 64 keys, K/V double-buffered via cp.async.
// qkv is pre-rounded tf32; y written tf32-rounded.
// ============================================================================
#define KP_STRIDE 68   // Ks / Ps / Q-stage stride (conflict-free frag loads)
#define V_STRIDE  72   // Vs stride (conflict-free b-frag loads)
#define ATTN_SMEM ((2*64*KP_STRIDE + 2*64*V_STRIDE + 128*KP_STRIDE) * (int)sizeof(float)) // 106496

__global__ __launch_bounds__(256, 2)
void attn_mma_kernel(const float* __restrict__ qkv, float* __restrict__ y)
{
    extern __shared__ float sm[];
    float* Ks0 = sm;
    float* Ks1 = sm + 64 * KP_STRIDE;
    float* Vs0 = sm + 2 * 64 * KP_STRIDE;
    float* Vs1 = Vs0 + 64 * V_STRIDE;
    float* Ps  = Vs0 + 2 * 64 * V_STRIDE;   // [128][KP_STRIDE], also Q staging
    float* KsA[2] = { Ks0, Ks1 };
    float* VsA[2] = { Vs0, Vs1 };

    const int tid  = threadIdx.x;
    const int wid  = tid >> 5;
    const int lane = tid & 31;
    const int lr = lane >> 2;    // 0..7
    const int lq = lane & 3;     // 0..3
    const int qt = blockIdx.x;   // 0..7  (128 rows each)
    const int bh = blockIdx.y;
    const int b = bh / NHEAD;
    const int h = bh % NHEAD;
    const int row_base = qt * 128;

    const float* qbase = qkv + ((size_t)(b * SEQ) + row_base) * C3 + h * HDIM;
    const float* kbase = qkv + (size_t)(b * SEQ) * C3 + CDIM + h * HDIM;
    const float* vbase = qkv + (size_t)(b * SEQ) * C3 + 2 * CDIM + h * HDIM;

    // Stage Q (pre-scaled by 1/8 — exact on tf32 values) into Ps, load a-frags
    for (int i = tid; i < 128 * 16; i += 256) {
        int r = i >> 4, c4 = (i & 15) << 2;
        float4 v = *(const float4*)(qbase + (size_t)r * C3 + c4);
        v.x *= 0.125f; v.y *= 0.125f; v.z *= 0.125f; v.w *= 0.125f;
        *(float4*)&Ps[r * KP_STRIDE + c4] = v;
    }
    __syncthreads();

    uint32_t aq[8][4];
    {
        const float* qp = Ps + (wid * 16) * KP_STRIDE;
        #pragma unroll
        for (int ks = 0; ks < 8; ks++) {
            aq[ks][0] = __float_as_uint(qp[lr * KP_STRIDE + ks * 8 + lq]);
            aq[ks][1] = __float_as_uint(qp[(lr + 8) * KP_STRIDE + ks * 8 + lq]);
            aq[ks][2] = __float_as_uint(qp[lr * KP_STRIDE + ks * 8 + 4 + lq]);
            aq[ks][3] = __float_as_uint(qp[(lr + 8) * KP_STRIDE + ks * 8 + 4 + lq]);
        }
    }
    __syncthreads();

    auto load_kv = [&](int buf, int kt) {
        const float* kb = kbase + (size_t)(kt * 64) * C3;
        const float* vb = vbase + (size_t)(kt * 64) * C3;
        const uint32_t kss = smem_u32(KsA[buf]);
        const uint32_t vss = smem_u32(VsA[buf]);
        #pragma unroll
        for (int i = 0; i < 4; i++) {
            int chunk = tid + 256 * i;        // 0..1023
            int r = chunk >> 4, c4 = (chunk & 15) << 2;
            cp_async16(kss + (uint32_t)(r * KP_STRIDE + c4) * 4,
                       kb + (size_t)r * C3 + c4);
            cp_async16(vss + (uint32_t)(r * V_STRIDE + c4) * 4,
                       vb + (size_t)r * C3 + c4);
        }
    };

    float m0 = -1e30f, m1 = -1e30f, l0 = 0.0f, l1 = 0.0f;
    float o[8][4];
    #pragma unroll
    for (int nt = 0; nt < 8; nt++)
        #pragma unroll
        for (int q = 0; q < 4; q++) o[nt][q] = 0.0f;

    const int nkt = 2 * qt + 2;
    const int warp_min_row = row_base + wid * 16;
    const int r0 = warp_min_row + lr;
    const int r1 = r0 + 8;
    float* Pw = Ps + (wid * 16) * KP_STRIDE;

    load_kv(0, 0);
    CP_COMMIT();

    for (int kt = 0; kt < nkt; kt++) {
        if (kt + 1 < nkt) {
            load_kv((kt + 1) & 1, kt + 1);
            CP_COMMIT();
            CP_WAIT(1);
        } else {
            CP_WAIT(0);
        }
        __syncthreads();

        const float* ks = KsA[kt & 1];
        const float* vs = VsA[kt & 1];

        // ---- S = (Q*scale) @ K^T  (64 HMMA) ----
        float s[8][4];
        #pragma unroll
        for (int nt = 0; nt < 8; nt++)
            #pragma unroll
            for (int q = 0; q < 4; q++) s[nt][q] = 0.0f;

        #pragma unroll
        for (int kd = 0; kd < 8; kd++) {
            #pragma unroll
            for (int nt = 0; nt < 8; nt++) {
                uint32_t bk[2];
                bk[0] = __float_as_uint(ks[(nt * 8 + lr) * KP_STRIDE + kd * 8 + lq]);
                bk[1] = __float_as_uint(ks[(nt * 8 + lr) * KP_STRIDE + kd * 8 + 4 + lq]);
                mma_tf32(s[nt], aq[kd], bk);
            }
        }

        // ---- causal mask (diagonal band only) ----
        if (kt * 64 + 63 > warp_min_row) {
            #pragma unroll
            for (int nt = 0; nt < 8; nt++) {
                const int c0 = kt * 64 + nt * 8 + 2 * lq;
                if (c0 > r0)     s[nt][0] = -1e30f;
                if (c0 + 1 > r0) s[nt][1] = -1e30f;
                if (c0 > r1)     s[nt][2] = -1e30f;
                if (c0 + 1 > r1) s[nt][3] = -1e30f;
            }
        }

        // ---- online softmax ----
        float mx0 = -1e30f, mx1 = -1e30f;
        #pragma unroll
        for (int nt = 0; nt < 8; nt++) {
            mx0 = fmaxf(mx0, fmaxf(s[nt][0], s[nt][1]));
            mx1 = fmaxf(mx1, fmaxf(s[nt][2], s[nt][3]));
        }
        mx0 = fmaxf(mx0, __shfl_xor_sync(0xffffffffu, mx0, 1));
        mx0 = fmaxf(mx0, __shfl_xor_sync(0xffffffffu, mx0, 2));
        mx1 = fmaxf(mx1, __shfl_xor_sync(0xffffffffu, mx1, 1));
        mx1 = fmaxf(mx1, __shfl_xor_sync(0xffffffffu, mx1, 2));

        const float mn0 = fmaxf(m0, mx0);
        const float mn1 = fmaxf(m1, mx1);
        const float a0 = __expf(m0 - mn0);
        const float a1 = __expf(m1 - mn1);
        m0 = mn0; m1 = mn1;

        float sum0 = 0.0f, sum1 = 0.0f;
        #pragma unroll
        for (int nt = 0; nt < 8; nt++) {
            float p00 = __expf(s[nt][0] - mn0);
            float p01 = __expf(s[nt][1] - mn0);
            float p10 = __expf(s[nt][2] - mn1);
            float p11 = __expf(s[nt][3] - mn1);
            sum0 += p00 + p01;
            sum1 += p10 + p11;
            // write P (tf32-rounded) to smem: rows lr / lr+8, cols nt*8+2lq
            *(float2*)&Pw[lr * KP_STRIDE + nt * 8 + 2 * lq] =
                make_float2(round_tf32(p00), round_tf32(p01));
            *(float2*)&Pw[(lr + 8) * KP_STRIDE + nt * 8 + 2 * lq] =
                make_float2(round_tf32(p10), round_tf32(p11));
        }
        sum0 += __shfl_xor_sync(0xffffffffu, sum0, 1);
        sum0 += __shfl_xor_sync(0xffffffffu, sum0, 2);
        sum1 += __shfl_xor_sync(0xffffffffu, sum1, 1);
        sum1 += __shfl_xor_sync(0xffffffffu, sum1, 2);
        l0 = l0 * a0 + sum0;
        l1 = l1 * a1 + sum1;

        #pragma unroll
        for (int nt = 0; nt < 8; nt++) {
            o[nt][0] *= a0; o[nt][1] *= a0;
            o[nt][2] *= a1; o[nt][3] *= a1;
        }
        __syncwarp();

        // ---- O += P @ V  (64 HMMA) ----
        #pragma unroll
        for (int kj = 0; kj < 8; kj++) {
            uint32_t ap[4];
            ap[0] = __float_as_uint(Pw[lr * KP_STRIDE + kj * 8 + lq]);
            ap[1] = __float_as_uint(Pw[(lr + 8) * KP_STRIDE + kj * 8 + lq]);
            ap[2] = __float_as_uint(Pw[lr * KP_STRIDE + kj * 8 + 4 + lq]);
            ap[3] = __float_as_uint(Pw[(lr + 8) * KP_STRIDE + kj * 8 + 4 + lq]);
            #pragma unroll
            for (int nt = 0; nt < 8; nt++) {
                uint32_t bv[2];
                bv[0] = __float_as_uint(vs[(kj * 8 + lq) * V_STRIDE + nt * 8 + lr]);
                bv[1] = __float_as_uint(vs[(kj * 8 + 4 + lq) * V_STRIDE + nt * 8 + lr]);
                mma_tf32(o[nt], ap, bv);
            }
        }
        __syncthreads();
    }

    // ---- epilogue: normalize, tf32-round (proj GEMM input), store ----
    const float inv0 = 1.0f / l0;
    const float inv1 = 1.0f / l1;
    float* y0 = y + (size_t)(b * SEQ + r0) * CDIM + h * HDIM;
    float* y1 = y + (size_t)(b * SEQ + r1) * CDIM + h * HDIM;
    #pragma unroll
    for (int nt = 0; nt < 8; nt++) {
        const int c = nt * 8 + 2 * lq;
        *(float2*)(y0 + c) = make_float2(round_tf32(o[nt][0] * inv0),
                                         round_tf32(o[nt][1] * inv0));
        *(float2*)(y1 + c) = make_float2(round_tf32(o[nt][2] * inv1),
                                         round_tf32(o[nt][3] * inv1));
    }
}

// ---------------------------------------------------------------------------
extern "C" void kernel_launch(void* const* d_in, const int* in_sizes, int n_in,
                              void* d_out, int out_size)
{
    const float* x      = (const float*)d_in[0];
    const float* W_attn = (const float*)d_in[1];
    const float* b_attn = (const float*)d_in[2];
    const float* W_proj = (const float*)d_in[3];
    const float* b_proj = (const float*)d_in[4];
    float* out = (float*)d_out;

    float *qkvp, *yp, *xt, *wa, *wp;
    cudaGetSymbolAddress((void**)&qkvp, g_qkv);
    cudaGetSymbolAddress((void**)&yp, g_y);
    cudaGetSymbolAddress((void**)&xt, g_xt);
    cudaGetSymbolAddress((void**)&wa, g_wa);
    cudaGetSymbolAddress((void**)&wp, g_wp);

    // 0) tf32 pre-round inputs
    round_kernel<<<(MTOT * CDIM) / 1024, 256>>>(x, xt, MTOT * CDIM);
    round_kernel<<<(CDIM * C3) / 1024, 256>>>(W_attn, wa, CDIM * C3);
    round_kernel<<<(CDIM * CDIM) / 1024, 256>>>(W_proj, wp, CDIM * CDIM);

    // 1) QKV projection; output tf32-rounded for attention
    {
        cudaFuncSetAttribute(gemm_mma_kernel<true>,
                             cudaFuncAttributeMaxDynamicSharedMemorySize,
                             GEMM_SMEM);
        dim3 grid(C3 / 128, MTOT / 128);
        gemm_mma_kernel<true><<<grid, 256, GEMM_SMEM>>>(xt, wa, b_attn, qkvp,
                                                        CDIM, C3);
    }

    // 2) Flash attention (tf32 mma)
    {
        cudaFuncSetAttribute(attn_mma_kernel,
                             cudaFuncAttributeMaxDynamicSharedMemorySize,
                             ATTN_SMEM);
        dim3 grid(SEQ / 128, BATCH * NHEAD);   // (8, 192)
        attn_mma_kernel<<<grid, 256, ATTN_SMEM>>>(qkvp, yp);
    }

    // 3) Output projection
    {
        cudaFuncSetAttribute(gemm_mma_kernel<false>,
                             cudaFuncAttributeMaxDynamicSharedMemorySize,
                             GEMM_SMEM);
        dim3 grid(CDIM / 128, MTOT / 128);
        gemm_mma_kernel<false><<<grid, 256, GEMM_SMEM>>>(yp, wp, b_proj, out,
                                                         CDIM, CDIM);
    }
}

// round 5
// speedup vs baseline: 5.9296x; 1.7994x over previous
#include <cuda_runtime.h>
#include <cuda_fp16.h>
#include <cstdint>
#include <math.h>

#define BATCH 16
#define SEQ   1024
#define CDIM  768
#define NHEAD 12
#define HDIM  64
#define C3    (3*CDIM)
#define MTOT  (BATCH*SEQ)

// Scratch (allocation-free rule: __device__ globals)
__device__ __half g_xh[(size_t)MTOT * CDIM];            // x,   half
__device__ __half g_yh[(size_t)MTOT * CDIM];            // attn out, half
__device__ __half g_qkvh[(size_t)MTOT * C3];            // q,k (v region unused)
__device__ __half g_vt[(size_t)BATCH * NHEAD * HDIM * SEQ]; // v transposed [b,h,d,t]
__device__ __half g_wat[(size_t)C3 * CDIM];             // W_attn^T [2304][768]
__device__ __half g_wpt[(size_t)CDIM * CDIM];           // W_proj^T [768][768]

// ============================================================================
// Baseline-PTX helpers
// ============================================================================
__device__ __forceinline__ uint32_t smem_u32(const void* p) {
    uint32_t a;
    asm("{ .reg .u64 t; cvta.to.shared.u64 t, %1; cvt.u32.u64 %0, t; }"
        : "=r"(a) : "l"(p));
    return a;
}
__device__ __forceinline__ void cp_async16(uint32_t dst, const void* src) {
    asm volatile("cp.async.cg.shared.global [%0], [%1], 16;"
                 :: "r"(dst), "l"(src));
}
#define CP_COMMIT() asm volatile("cp.async.commit_group;" ::: "memory")
#define CP_WAIT(n)  asm volatile("cp.async.wait_group %0;" :: "n"(n) : "memory")

__device__ __forceinline__ void mma_f16(float* d, const uint32_t* a,
                                        const uint32_t* b) {
    asm volatile(
        "mma.sync.aligned.m16n8k16.row.col.f32.f16.f16.f32 "
        "{%0,%1,%2,%3}, {%4,%5,%6,%7}, {%8,%9}, {%0,%1,%2,%3};"
        : "+f"(d[0]), "+f"(d[1]), "+f"(d[2]), "+f"(d[3])
        : "r"(a[0]), "r"(a[1]), "r"(a[2]), "r"(a[3]),
          "r"(b[0]), "r"(b[1]));
}
__device__ __forceinline__ uint32_t lds_u32(const __half* p) {
    return *reinterpret_cast<const uint32_t*>(p);
}

// ============================================================================
// Converts
// ============================================================================
__global__ void conv_h_kernel(const float* __restrict__ in,
                              __half* __restrict__ out, int n)
{
    int i = (blockIdx.x * 256 + threadIdx.x) * 4;
    if (i < n) {
        float4 v = *(const float4*)(in + i);
        __half2 h0 = __floats2half2_rn(v.x, v.y);
        __half2 h1 = __floats2half2_rn(v.z, v.w);
        uint2 u = make_uint2(*(uint32_t*)&h0, *(uint32_t*)&h1);
        *(uint2*)(out + i) = u;
    }
}

// out[n][k] = half(in[k][n]); in: [R][Ccols] f32
__global__ void convtrans_kernel(const float* __restrict__ in,
                                 __half* __restrict__ out, int R, int Ccols)
{
    __shared__ __half t[32][33];
    int c = blockIdx.x * 32 + threadIdx.x;
    int r = blockIdx.y * 32 + threadIdx.y;
    #pragma unroll
    for (int j = 0; j < 32; j += 8)
        t[threadIdx.y + j][threadIdx.x] = __float2half(in[(size_t)(r + j) * Ccols + c]);
    __syncthreads();
    int orow = blockIdx.x * 32 + threadIdx.y;
    int oc   = blockIdx.y * 32 + threadIdx.x;
    #pragma unroll
    for (int j = 0; j < 32; j += 8)
        out[(size_t)(orow + j) * R + oc] = t[threadIdx.x][threadIdx.y + j];
}

// ============================================================================
// fp16 mma GEMM: C[M,N] = A[M,K](half) @ Bt[N,K](half)^T + bias[N](f32)
// CTA 128x128, BK=64 halves, 256 threads, warp tile 64x32.
// OUT_MODE 0: write f32 to Cf.
// OUT_MODE 1: QKV epilogue — cols < 2C write half to Ch (row stride N);
//             cols >= 2C write transposed half to vt[b,h,d,t].
// ============================================================================
#define GST 72   // smem row stride in halves
#define GEMM_SMEM (4 * 128 * GST * 2)   // 73728 B (2 bufs x (A+B) x 128 x 72 x 2B)

template<int OUT_MODE>
__global__ __launch_bounds__(256, 2)
void gemm_h_kernel(const __half* __restrict__ A, const __half* __restrict__ Bt,
                   const float* __restrict__ bias, float* __restrict__ Cf,
                   __half* __restrict__ Ch, __half* __restrict__ vt,
                   int K, int N)
{
    extern __shared__ __half smh[];
    __half* As[2]  = { smh,            smh + 128 * GST };
    __half* Bs[2]  = { smh + 2*128*GST, smh + 3*128*GST };

    const int tid  = threadIdx.x;
    const int wid  = tid >> 5;
    const int lane = tid & 31;
    const int lr = lane >> 2;
    const int lq = lane & 3;
    const int bm = blockIdx.y * 128;
    const int bn = blockIdx.x * 128;
    const int warp_m = (wid & 1) * 64;
    const int warp_n = (wid >> 1) * 32;

    auto load_tile = [&](int buf, int it) {
        const int koff = it * 64;
        const uint32_t asb = smem_u32(As[buf]);
        const uint32_t bsb = smem_u32(Bs[buf]);
        #pragma unroll
        for (int i = 0; i < 4; ++i) {
            int chunk = tid + 256 * i;             // 0..1023
            int r = chunk >> 3, c8 = chunk & 7;    // row, 16B chunk
            cp_async16(asb + (uint32_t)(r * GST + c8 * 8) * 2,
                       A + (size_t)(bm + r) * K + koff + c8 * 8);
            cp_async16(bsb + (uint32_t)(r * GST + c8 * 8) * 2,
                       Bt + (size_t)(bn + r) * K + koff + c8 * 8);
        }
    };

    float acc[4][4][4];
    #pragma unroll
    for (int mi = 0; mi < 4; mi++)
        #pragma unroll
        for (int ni = 0; ni < 4; ni++)
            #pragma unroll
            for (int q = 0; q < 4; q++) acc[mi][ni][q] = 0.0f;

    const int nk = K / 64;
    load_tile(0, 0);
    CP_COMMIT();

    for (int it = 0; it < nk; ++it) {
        if (it + 1 < nk) {
            load_tile((it + 1) & 1, it + 1);
            CP_COMMIT();
            CP_WAIT(1);
        } else {
            CP_WAIT(0);
        }
        __syncthreads();

        const __half* as = As[it & 1];
        const __half* bs = Bs[it & 1];

        #pragma unroll
        for (int ks = 0; ks < 4; ks++) {
            const int k0 = ks * 16;
            uint32_t af[4][4];
            #pragma unroll
            for (int mi = 0; mi < 4; mi++) {
                const int r = warp_m + mi * 16 + lr;
                af[mi][0] = lds_u32(as + r * GST + k0 + 2 * lq);
                af[mi][1] = lds_u32(as + (r + 8) * GST + k0 + 2 * lq);
                af[mi][2] = lds_u32(as + r * GST + k0 + 8 + 2 * lq);
                af[mi][3] = lds_u32(as + (r + 8) * GST + k0 + 8 + 2 * lq);
            }
            uint32_t bf[4][2];
            #pragma unroll
            for (int ni = 0; ni < 4; ni++) {
                const int n = warp_n + ni * 8 + lr;
                bf[ni][0] = lds_u32(bs + n * GST + k0 + 2 * lq);
                bf[ni][1] = lds_u32(bs + n * GST + k0 + 8 + 2 * lq);
            }
            #pragma unroll
            for (int mi = 0; mi < 4; mi++)
                #pragma unroll
                for (int ni = 0; ni < 4; ni++)
                    mma_f16(acc[mi][ni], af[mi], bf[ni]);
        }
        __syncthreads();
    }

    // Epilogue
    const int lc2 = lq * 2;
    const bool is_v = (OUT_MODE == 1) && (bn >= 2 * CDIM);
    #pragma unroll
    for (int ni = 0; ni < 4; ni++) {
        const int col = bn + warp_n + ni * 8 + lc2;
        const float2 bv = *(const float2*)(bias + col);
        #pragma unroll
        for (int mi = 0; mi < 4; mi++) {
            const int row0 = bm + warp_m + mi * 16 + lr;
            float v00 = acc[mi][ni][0] + bv.x, v01 = acc[mi][ni][1] + bv.y;
            float v10 = acc[mi][ni][2] + bv.x, v11 = acc[mi][ni][3] + bv.y;
            if (OUT_MODE == 0) {
                *(float2*)(Cf + (size_t)row0 * N + col) = make_float2(v00, v01);
                *(float2*)(Cf + (size_t)(row0 + 8) * N + col) = make_float2(v10, v11);
            } else if (!is_v) {
                __half2 h0 = __floats2half2_rn(v00, v01);
                __half2 h1 = __floats2half2_rn(v10, v11);
                *(uint32_t*)(Ch + (size_t)row0 * N + col) = *(uint32_t*)&h0;
                *(uint32_t*)(Ch + (size_t)(row0 + 8) * N + col) = *(uint32_t*)&h1;
            } else {
                // V transposed: vt[((b*H + h)*HDIM + d)*SEQ + t]
                const int colv = col - 2 * CDIM;
                const int h = colv >> 6, d = colv & 63;
                #pragma unroll
                for (int rr = 0; rr < 2; rr++) {
                    const int row = row0 + rr * 8;
                    const int b = row >> 10, t = row & 1023;
                    __half* vp = vt + ((size_t)(b * NHEAD + h) * HDIM + d) * SEQ + t;
                    vp[0]   = __float2half(rr ? v10 : v00);
                    vp[SEQ] = __float2half(rr ? v11 : v01);
                }
            }
        }
    }
}

// ============================================================================
// Flash attention, fp16 mma m16n8k16.
// 256 threads, 128 q-rows per CTA (warp w: rows w*16..+15), 64-key tiles,
// K/V double-buffered cp.async. qkvh half; V from vt [b,h,d,t].
// ============================================================================
#define ATC 72   // smem stride (halves)
#define ATTN_SMEM ((2*64*ATC + 2*64*ATC + 128*ATC) * 2)   // 55296 B

__global__ __launch_bounds__(256, 2)
void attn_mma_kernel(const __half* __restrict__ qkv,
                     const __half* __restrict__ vt,
                     __half* __restrict__ y)
{
    extern __shared__ __half smh[];
    __half* KsA[2] = { smh,             smh + 64 * ATC };
    __half* VsA[2] = { smh + 2*64*ATC,  smh + 3*64*ATC };
    __half* Ps     = smh + 4*64*ATC;    // [128][ATC], also Q staging

    const int tid  = threadIdx.x;
    const int wid  = tid >> 5;
    const int lane = tid & 31;
    const int lr = lane >> 2;
    const int lq = lane & 3;
    const int qt = blockIdx.x;
    const int bh = blockIdx.y;
    const int b = bh / NHEAD;
    const int h = bh % NHEAD;
    const int row_base = qt * 128;

    const __half* qbase = qkv + ((size_t)(b * SEQ) + row_base) * C3 + h * HDIM;
    const __half* kbase = qkv + (size_t)(b * SEQ) * C3 + CDIM + h * HDIM;
    const __half* vbase = vt + (size_t)(b * NHEAD + h) * HDIM * SEQ;

    // Stage Q tile [128][64] via cp.async into Ps
    {
        const uint32_t ps = smem_u32(Ps);
        #pragma unroll
        for (int i = 0; i < 4; i++) {
            int chunk = tid + 256 * i;           // 0..1023
            int r = chunk >> 3, c8 = chunk & 7;
            cp_async16(ps + (uint32_t)(r * ATC + c8 * 8) * 2,
                       qbase + (size_t)r * C3 + c8 * 8);
        }
        CP_COMMIT();
        CP_WAIT(0);
    }
    __syncthreads();

    // Q a-frags (scaled by 1/8, exact in fp16)
    uint32_t aq[4][4];
    {
        const __half2 sc = __half2half2(__float2half(0.125f));
        const __half* qp = Ps + (wid * 16) * ATC;
        #pragma unroll
        for (int kd = 0; kd < 4; kd++) {
            const int k0 = kd * 16;
            __half2 t0 = *(const __half2*)(qp + lr * ATC + k0 + 2 * lq);
            __half2 t1 = *(const __half2*)(qp + (lr + 8) * ATC + k0 + 2 * lq);
            __half2 t2 = *(const __half2*)(qp + lr * ATC + k0 + 8 + 2 * lq);
            __half2 t3 = *(const __half2*)(qp + (lr + 8) * ATC + k0 + 8 + 2 * lq);
            t0 = __hmul2(t0, sc); t1 = __hmul2(t1, sc);
            t2 = __hmul2(t2, sc); t3 = __hmul2(t3, sc);
            aq[kd][0] = *(uint32_t*)&t0; aq[kd][1] = *(uint32_t*)&t1;
            aq[kd][2] = *(uint32_t*)&t2; aq[kd][3] = *(uint32_t*)&t3;
        }
    }
    __syncthreads();

    auto load_kv = [&](int buf, int kt) {
        const __half* kb = kbase + (size_t)(kt * 64) * C3;
        const __half* vb = vbase + kt * 64;
        const uint32_t kss = smem_u32(KsA[buf]);
        const uint32_t vss = smem_u32(VsA[buf]);
        #pragma unroll
        for (int i = 0; i < 2; i++) {
            int chunk = tid + 256 * i;           // 0..511
            int r = chunk >> 3, c8 = chunk & 7;  // key row / 16B chunk
            cp_async16(kss + (uint32_t)(r * ATC + c8 * 8) * 2,
                       kb + (size_t)r * C3 + c8 * 8);
            // V: rows d=0..63, cols t (contiguous)
            cp_async16(vss + (uint32_t)(r * ATC + c8 * 8) * 2,
                       vb + (size_t)r * SEQ + c8 * 8);
        }
    };

    float m0 = -1e30f, m1 = -1e30f, l0 = 0.0f, l1 = 0.0f;
    float o[8][4];
    #pragma unroll
    for (int nt = 0; nt < 8; nt++)
        #pragma unroll
        for (int q = 0; q < 4; q++) o[nt][q] = 0.0f;

    const int nkt = 2 * qt + 2;
    const int warp_min_row = row_base + wid * 16;
    const int r0 = warp_min_row + lr;
    const int r1 = r0 + 8;
    __half* Pw = Ps + (wid * 16) * ATC;

    load_kv(0, 0);
    CP_COMMIT();

    for (int kt = 0; kt < nkt; kt++) {
        if (kt + 1 < nkt) {
            load_kv((kt + 1) & 1, kt + 1);
            CP_COMMIT();
            CP_WAIT(1);
        } else {
            CP_WAIT(0);
        }
        __syncthreads();

        const __half* ks = KsA[kt & 1];
        const __half* vs = VsA[kt & 1];

        // ---- S = (Q*scale) @ K^T ----
        float s[8][4];
        #pragma unroll
        for (int nt = 0; nt < 8; nt++)
            #pragma unroll
            for (int q = 0; q < 4; q++) s[nt][q] = 0.0f;

        #pragma unroll
        for (int kd = 0; kd < 4; kd++) {
            const int k0 = kd * 16;
            #pragma unroll
            for (int nt = 0; nt < 8; nt++) {
                uint32_t bk[2];
                bk[0] = lds_u32(ks + (nt * 8 + lr) * ATC + k0 + 2 * lq);
                bk[1] = lds_u32(ks + (nt * 8 + lr) * ATC + k0 + 8 + 2 * lq);
                mma_f16(s[nt], aq[kd], bk);
            }
        }

        // ---- causal mask (diagonal band only) ----
        if (kt * 64 + 63 > warp_min_row) {
            #pragma unroll
            for (int nt = 0; nt < 8; nt++) {
                const int c0 = kt * 64 + nt * 8 + 2 * lq;
                if (c0 > r0)     s[nt][0] = -1e30f;
                if (c0 + 1 > r0) s[nt][1] = -1e30f;
                if (c0 > r1)     s[nt][2] = -1e30f;
                if (c0 + 1 > r1) s[nt][3] = -1e30f;
            }
        }

        // ---- online softmax ----
        float mx0 = -1e30f, mx1 = -1e30f;
        #pragma unroll
        for (int nt = 0; nt < 8; nt++) {
            mx0 = fmaxf(mx0, fmaxf(s[nt][0], s[nt][1]));
            mx1 = fmaxf(mx1, fmaxf(s[nt][2], s[nt][3]));
        }
        mx0 = fmaxf(mx0, __shfl_xor_sync(0xffffffffu, mx0, 1));
        mx0 = fmaxf(mx0, __shfl_xor_sync(0xffffffffu, mx0, 2));
        mx1 = fmaxf(mx1, __shfl_xor_sync(0xffffffffu, mx1, 1));
        mx1 = fmaxf(mx1, __shfl_xor_sync(0xffffffffu, mx1, 2));

        const float mn0 = fmaxf(m0, mx0);
        const float mn1 = fmaxf(m1, mx1);
        const float a0 = __expf(m0 - mn0);
        const float a1 = __expf(m1 - mn1);
        m0 = mn0; m1 = mn1;

        float sum0 = 0.0f, sum1 = 0.0f;
        #pragma unroll
        for (int nt = 0; nt < 8; nt++) {
            float p00 = __expf(s[nt][0] - mn0);
            float p01 = __expf(s[nt][1] - mn0);
            float p10 = __expf(s[nt][2] - mn1);
            float p11 = __expf(s[nt][3] - mn1);
            sum0 += p00 + p01;
            sum1 += p10 + p11;
            __half2 hp0 = __floats2half2_rn(p00, p01);
            __half2 hp1 = __floats2half2_rn(p10, p11);
            *(uint32_t*)(Pw + lr * ATC + nt * 8 + 2 * lq) = *(uint32_t*)&hp0;
            *(uint32_t*)(Pw + (lr + 8) * ATC + nt * 8 + 2 * lq) = *(uint32_t*)&hp1;
        }
        sum0 += __shfl_xor_sync(0xffffffffu, sum0, 1);
        sum0 += __shfl_xor_sync(0xffffffffu, sum0, 2);
        sum1 += __shfl_xor_sync(0xffffffffu, sum1, 1);
        sum1 += __shfl_xor_sync(0xffffffffu, sum1, 2);
        l0 = l0 * a0 + sum0;
        l1 = l1 * a1 + sum1;

        #pragma unroll
        for (int nt = 0; nt < 8; nt++) {
            o[nt][0] *= a0; o[nt][1] *= a0;
            o[nt][2] *= a1; o[nt][3] *= a1;
        }
        __syncwarp();

        // ---- O += P @ V ----
        #pragma unroll
        for (int kj = 0; kj < 4; kj++) {
            const int k0 = kj * 16;
            uint32_t ap[4];
            ap[0] = lds_u32(Pw + lr * ATC + k0 + 2 * lq);
            ap[1] = lds_u32(Pw + (lr + 8) * ATC + k0 + 2 * lq);
            ap[2] = lds_u32(Pw + lr * ATC + k0 + 8 + 2 * lq);
            ap[3] = lds_u32(Pw + (lr + 8) * ATC + k0 + 8 + 2 * lq);
            #pragma unroll
            for (int nt = 0; nt < 8; nt++) {
                uint32_t bv[2];
                bv[0] = lds_u32(vs + (nt * 8 + lr) * ATC + k0 + 2 * lq);
                bv[1] = lds_u32(vs + (nt * 8 + lr) * ATC + k0 + 8 + 2 * lq);
                mma_f16(o[nt], ap, bv);
            }
        }
        __syncthreads();
    }

    // ---- epilogue: normalize, store y as half ----
    const float inv0 = 1.0f / l0;
    const float inv1 = 1.0f / l1;
    __half* y0 = y + (size_t)(b * SEQ + r0) * CDIM + h * HDIM;
    __half* y1 = y + (size_t)(b * SEQ + r1) * CDIM + h * HDIM;
    #pragma unroll
    for (int nt = 0; nt < 8; nt++) {
        const int c = nt * 8 + 2 * lq;
        __half2 h0 = __floats2half2_rn(o[nt][0] * inv0, o[nt][1] * inv0);
        __half2 h1 = __floats2half2_rn(o[nt][2] * inv1, o[nt][3] * inv1);
        *(uint32_t*)(y0 + c) = *(uint32_t*)&h0;
        *(uint32_t*)(y1 + c) = *(uint32_t*)&h1;
    }
}

// ---------------------------------------------------------------------------
extern "C" void kernel_launch(void* const* d_in, const int* in_sizes, int n_in,
                              void* d_out, int out_size)
{
    const float* x      = (const float*)d_in[0];
    const float* W_attn = (const float*)d_in[1];
    const float* b_attn = (const float*)d_in[2];
    const float* W_proj = (const float*)d_in[3];
    const float* b_proj = (const float*)d_in[4];
    float* out = (float*)d_out;

    __half *xh, *yh, *qkvh, *vt, *wat, *wpt;
    cudaGetSymbolAddress((void**)&xh, g_xh);
    cudaGetSymbolAddress((void**)&yh, g_yh);
    cudaGetSymbolAddress((void**)&qkvh, g_qkvh);
    cudaGetSymbolAddress((void**)&vt, g_vt);
    cudaGetSymbolAddress((void**)&wat, g_wat);
    cudaGetSymbolAddress((void**)&wpt, g_wpt);

    // 0) converts: x -> half; weights -> transposed half
    conv_h_kernel<<<(MTOT * CDIM) / 1024, 256>>>(x, xh, MTOT * CDIM);
    {
        dim3 blk(32, 8);
        dim3 ga(C3 / 32, CDIM / 32);
        convtrans_kernel<<<ga, blk>>>(W_attn, wat, CDIM, C3);
        dim3 gp(CDIM / 32, CDIM / 32);
        convtrans_kernel<<<gp, blk>>>(W_proj, wpt, CDIM, CDIM);
    }

    // 1) QKV projection (fp16 mma); q,k -> qkvh; v -> vt transposed
    {
        cudaFuncSetAttribute(gemm_h_kernel<1>,
                             cudaFuncAttributeMaxDynamicSharedMemorySize,
                             GEMM_SMEM);
        dim3 grid(C3 / 128, MTOT / 128);
        gemm_h_kernel<1><<<grid, 256, GEMM_SMEM>>>(xh, wat, b_attn, nullptr,
                                                   qkvh, vt, CDIM, C3);
    }

    // 2) Flash attention (fp16 mma)
    {
        cudaFuncSetAttribute(attn_mma_kernel,
                             cudaFuncAttributeMaxDynamicSharedMemorySize,
                             ATTN_SMEM);
        dim3 grid(SEQ / 128, BATCH * NHEAD);
        attn_mma_kernel<<<grid, 256, ATTN_SMEM>>>(qkvh, vt, yh);
    }

    // 3) Output projection (fp16 mma, fp32 out)
    {
        cudaFuncSetAttribute(gemm_h_kernel<0>,
                             cudaFuncAttributeMaxDynamicSharedMemorySize,
                             GEMM_SMEM);
        dim3 grid(CDIM / 128, MTOT / 128);
        gemm_h_kernel<0><<<grid, 256, GEMM_SMEM>>>(yh, wpt, b_proj, out,
                                                   nullptr, nullptr,
                                                   CDIM, CDIM);
    }
}

// round 6
// speedup vs baseline: 6.9872x; 1.1784x over previous
#include <cuda_runtime.h>
#include <cuda_fp16.h>
#include <cstdint>
#include <math.h>

#define BATCH 16
#define SEQ   1024
#define CDIM  768
#define NHEAD 12
#define HDIM  64
#define C3    (3*CDIM)
#define MTOT  (BATCH*SEQ)

// Scratch (allocation-free rule: __device__ globals)
__device__ __half g_xh[(size_t)MTOT * CDIM];
__device__ __half g_yh[(size_t)MTOT * CDIM];
__device__ __half g_qkvh[(size_t)MTOT * C3];
__device__ __half g_vt[(size_t)BATCH * NHEAD * HDIM * SEQ]; // v [b,h,d,t]
__device__ __half g_wat[(size_t)C3 * CDIM];
__device__ __half g_wpt[(size_t)CDIM * CDIM];

// ============================================================================
// Baseline-PTX helpers
// ============================================================================
__device__ __forceinline__ uint32_t smem_u32(const void* p) {
    uint32_t a;
    asm("{ .reg .u64 t; cvta.to.shared.u64 t, %1; cvt.u32.u64 %0, t; }"
        : "=r"(a) : "l"(p));
    return a;
}
__device__ __forceinline__ void cp_async16(uint32_t dst, const void* src) {
    asm volatile("cp.async.cg.shared.global [%0], [%1], 16;"
                 :: "r"(dst), "l"(src));
}
#define CP_COMMIT() asm volatile("cp.async.commit_group;" ::: "memory")
#define CP_WAIT(n)  asm volatile("cp.async.wait_group %0;" :: "n"(n) : "memory")

__device__ __forceinline__ void mma_f16(float* d, const uint32_t* a,
                                        const uint32_t* b) {
    asm volatile(
        "mma.sync.aligned.m16n8k16.row.col.f32.f16.f16.f32 "
        "{%0,%1,%2,%3}, {%4,%5,%6,%7}, {%8,%9}, {%0,%1,%2,%3};"
        : "+f"(d[0]), "+f"(d[1]), "+f"(d[2]), "+f"(d[3])
        : "r"(a[0]), "r"(a[1]), "r"(a[2]), "r"(a[3]),
          "r"(b[0]), "r"(b[1]));
}
__device__ __forceinline__ void ldmatrix_x4(uint32_t* r, uint32_t addr) {
    asm volatile("ldmatrix.sync.aligned.m8n8.x4.shared.b16 {%0,%1,%2,%3}, [%4];"
        : "=r"(r[0]), "=r"(r[1]), "=r"(r[2]), "=r"(r[3]) : "r"(addr));
}

// ============================================================================
// Converts
// ============================================================================
__global__ void conv_h_kernel(const float* __restrict__ in,
                              __half* __restrict__ out, int n)
{
    int i = (blockIdx.x * 256 + threadIdx.x) * 4;
    if (i < n) {
        float4 v = *(const float4*)(in + i);
        __half2 h0 = __floats2half2_rn(v.x, v.y);
        __half2 h1 = __floats2half2_rn(v.z, v.w);
        uint2 u = make_uint2(*(uint32_t*)&h0, *(uint32_t*)&h1);
        *(uint2*)(out + i) = u;
    }
}

__global__ void convtrans_kernel(const float* __restrict__ in,
                                 __half* __restrict__ out, int R, int Ccols)
{
    __shared__ __half t[32][33];
    int c = blockIdx.x * 32 + threadIdx.x;
    int r = blockIdx.y * 32 + threadIdx.y;
    #pragma unroll
    for (int j = 0; j < 32; j += 8)
        t[threadIdx.y + j][threadIdx.x] = __float2half(in[(size_t)(r + j) * Ccols + c]);
    __syncthreads();
    int orow = blockIdx.x * 32 + threadIdx.y;
    int oc   = blockIdx.y * 32 + threadIdx.x;
    #pragma unroll
    for (int j = 0; j < 32; j += 8)
        out[(size_t)(orow + j) * R + oc] = t[threadIdx.x][threadIdx.y + j];
}

// ============================================================================
// fp16 mma GEMM with ldmatrix fragment loads.
// C[M,N] = A[M,K] @ Bt[N,K]^T + bias. CTA 128x128, BK=64, 256 thr.
// ============================================================================
#define GST 72
#define GEMM_SMEM (4 * 128 * GST * 2)   // 73728 B

template<int OUT_MODE>
__global__ __launch_bounds__(256, 2)
void gemm_h_kernel(const __half* __restrict__ A, const __half* __restrict__ Bt,
                   const float* __restrict__ bias, float* __restrict__ Cf,
                   __half* __restrict__ Ch, __half* __restrict__ vt,
                   int K, int N)
{
    extern __shared__ __half smh[];
    __half* As[2] = { smh,              smh + 128 * GST };
    __half* Bs[2] = { smh + 2*128*GST,  smh + 3*128*GST };

    const int tid  = threadIdx.x;
    const int wid  = tid >> 5;
    const int lane = tid & 31;
    const int lr = lane >> 2;
    const int lq = lane & 3;
    const int bm = blockIdx.y * 128;
    const int bn = blockIdx.x * 128;
    const int warp_m = (wid & 1) * 64;
    const int warp_n = (wid >> 1) * 32;

    // ldmatrix lane offsets (in halves, relative to tile base)
    const int l7 = lane & 7;
    const int gA_row = (lane >> 3) & 1;   // +8 rows for groups 1,3
    const int gA_k   = lane >> 4;         // +8 k for groups 2,3
    uint32_t aoff[4];
    #pragma unroll
    for (int mi = 0; mi < 4; mi++)
        aoff[mi] = (uint32_t)((warp_m + mi * 16 + l7 + gA_row * 8) * GST
                              + gA_k * 8);
    const int gB_k = (lane >> 3) & 1;     // +8 k for groups 1,3
    const int gB_n = lane >> 4;           // +8 n for groups 2,3
    uint32_t boff[2];
    #pragma unroll
    for (int nj = 0; nj < 2; nj++)
        boff[nj] = (uint32_t)((warp_n + nj * 16 + l7 + gB_n * 8) * GST
                              + gB_k * 8);

    auto load_tile = [&](int buf, int it) {
        const int koff = it * 64;
        const uint32_t asb = smem_u32(As[buf]);
        const uint32_t bsb = smem_u32(Bs[buf]);
        #pragma unroll
        for (int i = 0; i < 4; ++i) {
            int chunk = tid + 256 * i;
            int r = chunk >> 3, c8 = chunk & 7;
            cp_async16(asb + (uint32_t)(r * GST + c8 * 8) * 2,
                       A + (size_t)(bm + r) * K + koff + c8 * 8);
            cp_async16(bsb + (uint32_t)(r * GST + c8 * 8) * 2,
                       Bt + (size_t)(bn + r) * K + koff + c8 * 8);
        }
    };

    float acc[4][4][4];
    #pragma unroll
    for (int mi = 0; mi < 4; mi++)
        #pragma unroll
        for (int ni = 0; ni < 4; ni++)
            #pragma unroll
            for (int q = 0; q < 4; q++) acc[mi][ni][q] = 0.0f;

    const int nk = K / 64;
    load_tile(0, 0);
    CP_COMMIT();

    for (int it = 0; it < nk; ++it) {
        if (it + 1 < nk) {
            load_tile((it + 1) & 1, it + 1);
            CP_COMMIT();
            CP_WAIT(1);
        } else {
            CP_WAIT(0);
        }
        __syncthreads();

        const uint32_t asb = smem_u32(As[it & 1]);
        const uint32_t bsb = smem_u32(Bs[it & 1]);

        #pragma unroll
        for (int ks = 0; ks < 4; ks++) {
            const int k0 = ks * 16;
            uint32_t af[4][4];
            #pragma unroll
            for (int mi = 0; mi < 4; mi++)
                ldmatrix_x4(af[mi], asb + (aoff[mi] + k0) * 2);
            uint32_t bf[2][4];   // [nj][b(2ni) regs]
            #pragma unroll
            for (int nj = 0; nj < 2; nj++)
                ldmatrix_x4(bf[nj], bsb + (boff[nj] + k0) * 2);
            #pragma unroll
            for (int mi = 0; mi < 4; mi++)
                #pragma unroll
                for (int ni = 0; ni < 4; ni++)
                    mma_f16(acc[mi][ni], af[mi], &bf[ni >> 1][(ni & 1) * 2]);
        }
        __syncthreads();
    }

    // Epilogue
    const int lc2 = lq * 2;
    const bool is_v = (OUT_MODE == 1) && (bn >= 2 * CDIM);
    #pragma unroll
    for (int ni = 0; ni < 4; ni++) {
        const int col = bn + warp_n + ni * 8 + lc2;
        const float2 bv = *(const float2*)(bias + col);
        #pragma unroll
        for (int mi = 0; mi < 4; mi++) {
            const int row0 = bm + warp_m + mi * 16 + lr;
            float v00 = acc[mi][ni][0] + bv.x, v01 = acc[mi][ni][1] + bv.y;
            float v10 = acc[mi][ni][2] + bv.x, v11 = acc[mi][ni][3] + bv.y;
            if (OUT_MODE == 0) {
                *(float2*)(Cf + (size_t)row0 * N + col) = make_float2(v00, v01);
                *(float2*)(Cf + (size_t)(row0 + 8) * N + col) = make_float2(v10, v11);
            } else if (!is_v) {
                __half2 h0 = __floats2half2_rn(v00, v01);
                __half2 h1 = __floats2half2_rn(v10, v11);
                *(uint32_t*)(Ch + (size_t)row0 * N + col) = *(uint32_t*)&h0;
                *(uint32_t*)(Ch + (size_t)(row0 + 8) * N + col) = *(uint32_t*)&h1;
            } else {
                const int colv = col - 2 * CDIM;
                const int h = colv >> 6, d = colv & 63;
                #pragma unroll
                for (int rr = 0; rr < 2; rr++) {
                    const int row = row0 + rr * 8;
                    const int b = row >> 10, t = row & 1023;
                    __half* vp = vt + ((size_t)(b * NHEAD + h) * HDIM + d) * SEQ + t;
                    vp[0]   = __float2half(rr ? v10 : v00);
                    vp[SEQ] = __float2half(rr ? v11 : v01);
                }
            }
        }
    }
}

// ============================================================================
// Flash attention, fp16 mma + ldmatrix.
// ============================================================================
#define ATC 72
#define ATTN_SMEM ((2*64*ATC + 2*64*ATC + 128*ATC) * 2)   // 55296 B

__global__ __launch_bounds__(256, 2)
void attn_mma_kernel(const __half* __restrict__ qkv,
                     const __half* __restrict__ vt,
                     __half* __restrict__ y)
{
    extern __shared__ __half smh[];
    __half* KsA[2] = { smh,             smh + 64 * ATC };
    __half* VsA[2] = { smh + 2*64*ATC,  smh + 3*64*ATC };
    __half* Ps     = smh + 4*64*ATC;

    const int tid  = threadIdx.x;
    const int wid  = tid >> 5;
    const int lane = tid & 31;
    const int lr = lane >> 2;
    const int lq = lane & 3;
    const int qt = blockIdx.x;
    const int bh = blockIdx.y;
    const int b = bh / NHEAD;
    const int h = bh % NHEAD;
    const int row_base = qt * 128;

    const __half* qbase = qkv + ((size_t)(b * SEQ) + row_base) * C3 + h * HDIM;
    const __half* kbase = qkv + (size_t)(b * SEQ) * C3 + CDIM + h * HDIM;
    const __half* vbase = vt + (size_t)(b * NHEAD + h) * HDIM * SEQ;

    // ldmatrix lane offsets
    const int l7 = lane & 7;
    const uint32_t a_off = (uint32_t)((wid * 16 + l7 + ((lane >> 3) & 1) * 8) * ATC
                                      + (lane >> 4) * 8);     // A-frag (Q / P)
    uint32_t b_off[4];                                         // B-frag (K / V), per nt-pair
    #pragma unroll
    for (int np = 0; np < 4; np++)
        b_off[np] = (uint32_t)((np * 16 + l7 + (lane >> 4) * 8) * ATC
                               + ((lane >> 3) & 1) * 8);

    // Stage Q tile [128][64]
    {
        const uint32_t ps = smem_u32(Ps);
        #pragma unroll
        for (int i = 0; i < 4; i++) {
            int chunk = tid + 256 * i;
            int r = chunk >> 3, c8 = chunk & 7;
            cp_async16(ps + (uint32_t)(r * ATC + c8 * 8) * 2,
                       qbase + (size_t)r * C3 + c8 * 8);
        }
        CP_COMMIT();
        CP_WAIT(0);
    }
    __syncthreads();

    // Q a-frags via ldmatrix, scaled by 1/8 (exact in fp16)
    uint32_t aq[4][4];
    {
        const uint32_t ps = smem_u32(Ps);
        const __half2 sc = __half2half2(__float2half(0.125f));
        #pragma unroll
        for (int kd = 0; kd < 4; kd++) {
            ldmatrix_x4(aq[kd], ps + (a_off + kd * 16) * 2);
            #pragma unroll
            for (int q = 0; q < 4; q++) {
                __half2 t = *(__half2*)&aq[kd][q];
                t = __hmul2(t, sc);
                aq[kd][q] = *(uint32_t*)&t;
            }
        }
    }
    __syncthreads();

    auto load_kv = [&](int buf, int kt) {
        const __half* kb = kbase + (size_t)(kt * 64) * C3;
        const __half* vb = vbase + kt * 64;
        const uint32_t kss = smem_u32(KsA[buf]);
        const uint32_t vss = smem_u32(VsA[buf]);
        #pragma unroll
        for (int i = 0; i < 2; i++) {
            int chunk = tid + 256 * i;
            int r = chunk >> 3, c8 = chunk & 7;
            cp_async16(kss + (uint32_t)(r * ATC + c8 * 8) * 2,
                       kb + (size_t)r * C3 + c8 * 8);
            cp_async16(vss + (uint32_t)(r * ATC + c8 * 8) * 2,
                       vb + (size_t)r * SEQ + c8 * 8);
        }
    };

    float m0 = -1e30f, m1 = -1e30f, l0 = 0.0f, l1 = 0.0f;
    float o[8][4];
    #pragma unroll
    for (int nt = 0; nt < 8; nt++)
        #pragma unroll
        for (int q = 0; q < 4; q++) o[nt][q] = 0.0f;

    const int nkt = 2 * qt + 2;
    const int warp_min_row = row_base + wid * 16;
    const int r0 = warp_min_row + lr;
    const int r1 = r0 + 8;
    __half* Pw = Ps + (wid * 16) * ATC;

    load_kv(0, 0);
    CP_COMMIT();

    for (int kt = 0; kt < nkt; kt++) {
        if (kt + 1 < nkt) {
            load_kv((kt + 1) & 1, kt + 1);
            CP_COMMIT();
            CP_WAIT(1);
        } else {
            CP_WAIT(0);
        }
        __syncthreads();

        const uint32_t kss = smem_u32(KsA[kt & 1]);
        const uint32_t vss = smem_u32(VsA[kt & 1]);

        // ---- S = (Q*scale) @ K^T ----
        float s[8][4];
        #pragma unroll
        for (int nt = 0; nt < 8; nt++)
            #pragma unroll
            for (int q = 0; q < 4; q++) s[nt][q] = 0.0f;

        #pragma unroll
        for (int kd = 0; kd < 4; kd++) {
            #pragma unroll
            for (int np = 0; np < 4; np++) {
                uint32_t bk[4];
                ldmatrix_x4(bk, kss + (b_off[np] + kd * 16) * 2);
                mma_f16(s[2 * np],     aq[kd], &bk[0]);
                mma_f16(s[2 * np + 1], aq[kd], &bk[2]);
            }
        }

        // ---- causal mask (diagonal band only) ----
        if (kt * 64 + 63 > warp_min_row) {
            #pragma unroll
            for (int nt = 0; nt < 8; nt++) {
                const int c0 = kt * 64 + nt * 8 + 2 * lq;
                if (c0 > r0)     s[nt][0] = -1e30f;
                if (c0 + 1 > r0) s[nt][1] = -1e30f;
                if (c0 > r1)     s[nt][2] = -1e30f;
                if (c0 + 1 > r1) s[nt][3] = -1e30f;
            }
        }

        // ---- online softmax ----
        float mx0 = -1e30f, mx1 = -1e30f;
        #pragma unroll
        for (int nt = 0; nt < 8; nt++) {
            mx0 = fmaxf(mx0, fmaxf(s[nt][0], s[nt][1]));
            mx1 = fmaxf(mx1, fmaxf(s[nt][2], s[nt][3]));
        }
        mx0 = fmaxf(mx0, __shfl_xor_sync(0xffffffffu, mx0, 1));
        mx0 = fmaxf(mx0, __shfl_xor_sync(0xffffffffu, mx0, 2));
        mx1 = fmaxf(mx1, __shfl_xor_sync(0xffffffffu, mx1, 1));
        mx1 = fmaxf(mx1, __shfl_xor_sync(0xffffffffu, mx1, 2));

        const float mn0 = fmaxf(m0, mx0);
        const float mn1 = fmaxf(m1, mx1);
        const float a0 = __expf(m0 - mn0);
        const float a1 = __expf(m1 - mn1);
        m0 = mn0; m1 = mn1;

        float sum0 = 0.0f, sum1 = 0.0f;
        #pragma unroll
        for (int nt = 0; nt < 8; nt++) {
            float p00 = __expf(s[nt][0] - mn0);
            float p01 = __expf(s[nt][1] - mn0);
            float p10 = __expf(s[nt][2] - mn1);
            float p11 = __expf(s[nt][3] - mn1);
            sum0 += p00 + p01;
            sum1 += p10 + p11;
            __half2 hp0 = __floats2half2_rn(p00, p01);
            __half2 hp1 = __floats2half2_rn(p10, p11);
            *(uint32_t*)(Pw + lr * ATC + nt * 8 + 2 * lq) = *(uint32_t*)&hp0;
            *(uint32_t*)(Pw + (lr + 8) * ATC + nt * 8 + 2 * lq) = *(uint32_t*)&hp1;
        }
        sum0 += __shfl_xor_sync(0xffffffffu, sum0, 1);
        sum0 += __shfl_xor_sync(0xffffffffu, sum0, 2);
        sum1 += __shfl_xor_sync(0xffffffffu, sum1, 1);
        sum1 += __shfl_xor_sync(0xffffffffu, sum1, 2);
        l0 = l0 * a0 + sum0;
        l1 = l1 * a1 + sum1;

        #pragma unroll
        for (int nt = 0; nt < 8; nt++) {
            o[nt][0] *= a0; o[nt][1] *= a0;
            o[nt][2] *= a1; o[nt][3] *= a1;
        }
        __syncwarp();

        // ---- O += P @ V ----
        const uint32_t psb = smem_u32(Ps);
        #pragma unroll
        for (int kj = 0; kj < 4; kj++) {
            uint32_t ap[4];
            ldmatrix_x4(ap, psb + (a_off + kj * 16) * 2);
            #pragma unroll
            for (int np = 0; np < 4; np++) {
                uint32_t bv[4];
                ldmatrix_x4(bv, vss + (b_off[np] + kj * 16) * 2);
                mma_f16(o[2 * np],     ap, &bv[0]);
                mma_f16(o[2 * np + 1], ap, &bv[2]);
            }
        }
        __syncthreads();
    }

    // ---- epilogue ----
    const float inv0 = 1.0f / l0;
    const float inv1 = 1.0f / l1;
    __half* y0 = y + (size_t)(b * SEQ + r0) * CDIM + h * HDIM;
    __half* y1 = y + (size_t)(b * SEQ + r1) * CDIM + h * HDIM;
    #pragma unroll
    for (int nt = 0; nt < 8; nt++) {
        const int c = nt * 8 + 2 * lq;
        __half2 h0 = __floats2half2_rn(o[nt][0] * inv0, o[nt][1] * inv0);
        __half2 h1 = __floats2half2_rn(o[nt][2] * inv1, o[nt][3] * inv1);
        *(uint32_t*)(y0 + c) = *(uint32_t*)&h0;
        *(uint32_t*)(y1 + c) = *(uint32_t*)&h1;
    }
}

// ---------------------------------------------------------------------------
extern "C" void kernel_launch(void* const* d_in, const int* in_sizes, int n_in,
                              void* d_out, int out_size)
{
    const float* x      = (const float*)d_in[0];
    const float* W_attn = (const float*)d_in[1];
    const float* b_attn = (const float*)d_in[2];
    const float* W_proj = (const float*)d_in[3];
    const float* b_proj = (const float*)d_in[4];
    float* out = (float*)d_out;

    __half *xh, *yh, *qkvh, *vt, *wat, *wpt;
    cudaGetSymbolAddress((void**)&xh, g_xh);
    cudaGetSymbolAddress((void**)&yh, g_yh);
    cudaGetSymbolAddress((void**)&qkvh, g_qkvh);
    cudaGetSymbolAddress((void**)&vt, g_vt);
    cudaGetSymbolAddress((void**)&wat, g_wat);
    cudaGetSymbolAddress((void**)&wpt, g_wpt);

    conv_h_kernel<<<(MTOT * CDIM) / 1024, 256>>>(x, xh, MTOT * CDIM);
    {
        dim3 blk(32, 8);
        dim3 ga(C3 / 32, CDIM / 32);
        convtrans_kernel<<<ga, blk>>>(W_attn, wat, CDIM, C3);
        dim3 gp(CDIM / 32, CDIM / 32);
        convtrans_kernel<<<gp, blk>>>(W_proj, wpt, CDIM, CDIM);
    }

    {
        cudaFuncSetAttribute(gemm_h_kernel<1>,
                             cudaFuncAttributeMaxDynamicSharedMemorySize,
                             GEMM_SMEM);
        dim3 grid(C3 / 128, MTOT / 128);
        gemm_h_kernel<1><<<grid, 256, GEMM_SMEM>>>(xh, wat, b_attn, nullptr,
                                                   qkvh, vt, CDIM, C3);
    }
    {
        cudaFuncSetAttribute(attn_mma_kernel,
                             cudaFuncAttributeMaxDynamicSharedMemorySize,
                             ATTN_SMEM);
        dim3 grid(SEQ / 128, BATCH * NHEAD);
        attn_mma_kernel<<<grid, 256, ATTN_SMEM>>>(qkvh, vt, yh);
    }
    {
        cudaFuncSetAttribute(gemm_h_kernel<0>,
                             cudaFuncAttributeMaxDynamicSharedMemorySize,
                             GEMM_SMEM);
        dim3 grid(CDIM / 128, MTOT / 128);
        gemm_h_kernel<0><<<grid, 256, GEMM_SMEM>>>(yh, wpt, b_proj, out,
                                                   nullptr, nullptr,
                                                   CDIM, CDIM);
    }
}

// round 7
// speedup vs baseline: 7.2719x; 1.0407x over previous
#include <cuda_runtime.h>
#include <cuda_fp16.h>
#include <cstdint>
#include <math.h>

#define BATCH 16
#define SEQ   1024
#define CDIM  768
#define NHEAD 12
#define HDIM  64
#define C3    (3*CDIM)
#define MTOT  (BATCH*SEQ)

// Scratch (allocation-free rule: __device__ globals)
__device__ __half g_xh[(size_t)MTOT * CDIM];
__device__ __half g_yh[(size_t)MTOT * CDIM];
__device__ __half g_qkvh[(size_t)MTOT * C3];
__device__ __half g_vt[(size_t)BATCH * NHEAD * HDIM * SEQ]; // v [b,h,d,t]
__device__ __half g_wat[(size_t)C3 * CDIM];
__device__ __half g_wpt[(size_t)CDIM * CDIM];

// ============================================================================
// Baseline-PTX helpers
// ============================================================================
__device__ __forceinline__ uint32_t smem_u32(const void* p) {
    uint32_t a;
    asm("{ .reg .u64 t; cvta.to.shared.u64 t, %1; cvt.u32.u64 %0, t; }"
        : "=r"(a) : "l"(p));
    return a;
}
__device__ __forceinline__ void cp_async16(uint32_t dst, const void* src) {
    asm volatile("cp.async.cg.shared.global [%0], [%1], 16;"
                 :: "r"(dst), "l"(src));
}
#define CP_COMMIT() asm volatile("cp.async.commit_group;" ::: "memory")
#define CP_WAIT(n)  asm volatile("cp.async.wait_group %0;" :: "n"(n) : "memory")

__device__ __forceinline__ void mma_f16(float* d, const uint32_t* a,
                                        const uint32_t* b) {
    asm volatile(
        "mma.sync.aligned.m16n8k16.row.col.f32.f16.f16.f32 "
        "{%0,%1,%2,%3}, {%4,%5,%6,%7}, {%8,%9}, {%0,%1,%2,%3};"
        : "+f"(d[0]), "+f"(d[1]), "+f"(d[2]), "+f"(d[3])
        : "r"(a[0]), "r"(a[1]), "r"(a[2]), "r"(a[3]),
          "r"(b[0]), "r"(b[1]));
}
__device__ __forceinline__ void ldmatrix_x4(uint32_t* r, uint32_t addr) {
    asm volatile("ldmatrix.sync.aligned.m8n8.x4.shared.b16 {%0,%1,%2,%3}, [%4];"
        : "=r"(r[0]), "=r"(r[1]), "=r"(r[2]), "=r"(r[3]) : "r"(addr));
}

// ============================================================================
// Converts
// ============================================================================
__global__ void conv_h_kernel(const float* __restrict__ in,
                              __half* __restrict__ out, int n)
{
    int i = (blockIdx.x * 256 + threadIdx.x) * 4;
    if (i < n) {
        float4 v = *(const float4*)(in + i);
        __half2 h0 = __floats2half2_rn(v.x, v.y);
        __half2 h1 = __floats2half2_rn(v.z, v.w);
        uint2 u = make_uint2(*(uint32_t*)&h0, *(uint32_t*)&h1);
        *(uint2*)(out + i) = u;
    }
}

__global__ void convtrans_kernel(const float* __restrict__ in,
                                 __half* __restrict__ out, int R, int Ccols)
{
    __shared__ __half t[32][33];
    int c = blockIdx.x * 32 + threadIdx.x;
    int r = blockIdx.y * 32 + threadIdx.y;
    #pragma unroll
    for (int j = 0; j < 32; j += 8)
        t[threadIdx.y + j][threadIdx.x] = __float2half(in[(size_t)(r + j) * Ccols + c]);
    __syncthreads();
    int orow = blockIdx.x * 32 + threadIdx.y;
    int oc   = blockIdx.y * 32 + threadIdx.x;
    #pragma unroll
    for (int j = 0; j < 32; j += 8)
        out[(size_t)(orow + j) * R + oc] = t[threadIdx.x][threadIdx.y + j];
}

// ============================================================================
// fp16 mma GEMM, ldmatrix fragments, 3-stage cp.async (1 barrier / iter).
// C[M,N] = A[M,K] @ Bt[N,K]^T + bias. CTA 128x128, BK=64, 256 thr.
// ============================================================================
#define GST 72
#define NST 3
#define STAGE_H (2 * 128 * GST)                 // halves per stage (A+B)
#define GEMM_SMEM (NST * STAGE_H * 2)           // 110592 B
#define VTS 136                                 // V epilogue transpose stride

template<int OUT_MODE>
__global__ __launch_bounds__(256, 2)
void gemm_h_kernel(const __half* __restrict__ A, const __half* __restrict__ Bt,
                   const float* __restrict__ bias, float* __restrict__ Cf,
                   __half* __restrict__ Ch, __half* __restrict__ vt,
                   int K, int N)
{
    extern __shared__ __half smh[];

    const int tid  = threadIdx.x;
    const int wid  = tid >> 5;
    const int lane = tid & 31;
    const int lr = lane >> 2;
    const int lq = lane & 3;
    const int bm = blockIdx.y * 128;
    const int bn = blockIdx.x * 128;
    const int warp_m = (wid & 1) * 64;
    const int warp_n = (wid >> 1) * 32;

    const int l7 = lane & 7;
    const int gA_row = (lane >> 3) & 1;
    const int gA_k   = lane >> 4;
    uint32_t aoff[4];
    #pragma unroll
    for (int mi = 0; mi < 4; mi++)
        aoff[mi] = (uint32_t)((warp_m + mi * 16 + l7 + gA_row * 8) * GST
                              + gA_k * 8);
    const int gB_k = (lane >> 3) & 1;
    const int gB_n = lane >> 4;
    uint32_t boff[2];
    #pragma unroll
    for (int nj = 0; nj < 2; nj++)
        boff[nj] = (uint32_t)((warp_n + nj * 16 + l7 + gB_n * 8) * GST
                              + gB_k * 8);

    const uint32_t smb = smem_u32(smh);

    auto load_tile = [&](int st, int it) {
        const int koff = it * 64;
        const uint32_t asb = smb + (uint32_t)(st * STAGE_H) * 2;
        const uint32_t bsb = asb + (uint32_t)(128 * GST) * 2;
        #pragma unroll
        for (int i = 0; i < 4; ++i) {
            int chunk = tid + 256 * i;
            int r = chunk >> 3, c8 = chunk & 7;
            cp_async16(asb + (uint32_t)(r * GST + c8 * 8) * 2,
                       A + (size_t)(bm + r) * K + koff + c8 * 8);
            cp_async16(bsb + (uint32_t)(r * GST + c8 * 8) * 2,
                       Bt + (size_t)(bn + r) * K + koff + c8 * 8);
        }
    };

    float acc[4][4][4];
    #pragma unroll
    for (int mi = 0; mi < 4; mi++)
        #pragma unroll
        for (int ni = 0; ni < 4; ni++)
            #pragma unroll
            for (int q = 0; q < 4; q++) acc[mi][ni][q] = 0.0f;

    const int nk = K / 64;            // >= 2 always here
    load_tile(0, 0);
    CP_COMMIT();
    load_tile(1, 1);
    CP_COMMIT();

    for (int it = 0; it < nk; ++it) {
        CP_WAIT(1);
        __syncthreads();
        if (it + 2 < nk) load_tile((it + 2) % NST, it + 2);
        CP_COMMIT();

        const int st = it % NST;
        const uint32_t asb = smb + (uint32_t)(st * STAGE_H) * 2;
        const uint32_t bsb = asb + (uint32_t)(128 * GST) * 2;

        #pragma unroll
        for (int ks = 0; ks < 4; ks++) {
            const int k0 = ks * 16;
            uint32_t af[4][4];
            #pragma unroll
            for (int mi = 0; mi < 4; mi++)
                ldmatrix_x4(af[mi], asb + (aoff[mi] + k0) * 2);
            uint32_t bf[2][4];
            #pragma unroll
            for (int nj = 0; nj < 2; nj++)
                ldmatrix_x4(bf[nj], bsb + (boff[nj] + k0) * 2);
            #pragma unroll
            for (int mi = 0; mi < 4; mi++)
                #pragma unroll
                for (int ni = 0; ni < 4; ni++)
                    mma_f16(acc[mi][ni], af[mi], &bf[ni >> 1][(ni & 1) * 2]);
        }
    }

    // Epilogue
    const int lc2 = lq * 2;
    const bool is_v = (OUT_MODE == 1) && (bn >= 2 * CDIM);

    if (is_v) {
        // Stage V tile in smem transposed [col][row], then coalesced store.
        __syncthreads();
        __half* Vt = smh;   // 128 x VTS halves = 34816 B, fits stage area
        #pragma unroll
        for (int ni = 0; ni < 4; ni++) {
            const int c = warp_n + ni * 8 + lc2;
            const float2 bv = *(const float2*)(bias + bn + c);
            #pragma unroll
            for (int mi = 0; mi < 4; mi++) {
                const int r = warp_m + mi * 16 + lr;
                Vt[(c    ) * VTS + r    ] = __float2half(acc[mi][ni][0] + bv.x);
                Vt[(c + 1) * VTS + r    ] = __float2half(acc[mi][ni][1] + bv.y);
                Vt[(c    ) * VTS + r + 8] = __float2half(acc[mi][ni][2] + bv.x);
                Vt[(c + 1) * VTS + r + 8] = __float2half(acc[mi][ni][3] + bv.y);
            }
        }
        __syncthreads();
        const int b = bm >> 10;
        const int t0 = bm & 1023;
        for (int i = tid; i < 128 * 16; i += 256) {
            const int c  = i >> 4;           // local col (d within 2 heads)
            const int x8 = (i & 15) * 8;     // t offset (8 halves)
            const int colv = bn - 2 * CDIM + c;
            const int h = colv >> 6, d = colv & 63;
            uint4 val = *(const uint4*)&Vt[c * VTS + x8];
            *(uint4*)(vt + ((size_t)(b * NHEAD + h) * HDIM + d) * SEQ + t0 + x8) = val;
        }
        return;
    }

    #pragma unroll
    for (int ni = 0; ni < 4; ni++) {
        const int col = bn + warp_n + ni * 8 + lc2;
        const float2 bv = *(const float2*)(bias + col);
        #pragma unroll
        for (int mi = 0; mi < 4; mi++) {
            const int row0 = bm + warp_m + mi * 16 + lr;
            float v00 = acc[mi][ni][0] + bv.x, v01 = acc[mi][ni][1] + bv.y;
            float v10 = acc[mi][ni][2] + bv.x, v11 = acc[mi][ni][3] + bv.y;
            if (OUT_MODE == 0) {
                *(float2*)(Cf + (size_t)row0 * N + col) = make_float2(v00, v01);
                *(float2*)(Cf + (size_t)(row0 + 8) * N + col) = make_float2(v10, v11);
            } else {
                __half2 h0 = __floats2half2_rn(v00, v01);
                __half2 h1 = __floats2half2_rn(v10, v11);
                *(uint32_t*)(Ch + (size_t)row0 * N + col) = *(uint32_t*)&h0;
                *(uint32_t*)(Ch + (size_t)(row0 + 8) * N + col) = *(uint32_t*)&h1;
            }
        }
    }
}

// ============================================================================
// Flash attention, fp16 mma + ldmatrix, 3-stage cp.async K/V pipeline.
// ============================================================================
#define ATC 72
#define AKV_H (64 * ATC)                       // halves per K (or V) stage
#define ATTN_SMEM ((6 * AKV_H + 128 * ATC) * 2)  // 73728 B

__global__ __launch_bounds__(256, 2)
void attn_mma_kernel(const __half* __restrict__ qkv,
                     const __half* __restrict__ vt,
                     __half* __restrict__ y)
{
    extern __shared__ __half smh[];
    __half* Ps = smh + 6 * AKV_H;

    const int tid  = threadIdx.x;
    const int wid  = tid >> 5;
    const int lane = tid & 31;
    const int lr = lane >> 2;
    const int lq = lane & 3;
    const int qt = blockIdx.x;
    const int bh = blockIdx.y;
    const int b = bh / NHEAD;
    const int h = bh % NHEAD;
    const int row_base = qt * 128;

    const __half* qbase = qkv + ((size_t)(b * SEQ) + row_base) * C3 + h * HDIM;
    const __half* kbase = qkv + (size_t)(b * SEQ) * C3 + CDIM + h * HDIM;
    const __half* vbase = vt + (size_t)(b * NHEAD + h) * HDIM * SEQ;

    const int l7 = lane & 7;
    const uint32_t a_off = (uint32_t)((wid * 16 + l7 + ((lane >> 3) & 1) * 8) * ATC
                                      + (lane >> 4) * 8);
    uint32_t b_off[4];
    #pragma unroll
    for (int np = 0; np < 4; np++)
        b_off[np] = (uint32_t)((np * 16 + l7 + (lane >> 4) * 8) * ATC
                               + ((lane >> 3) & 1) * 8);

    const uint32_t smb = smem_u32(smh);
    const uint32_t psb = smem_u32(Ps);

    // Stage Q tile [128][64]
    {
        #pragma unroll
        for (int i = 0; i < 4; i++) {
            int chunk = tid + 256 * i;
            int r = chunk >> 3, c8 = chunk & 7;
            cp_async16(psb + (uint32_t)(r * ATC + c8 * 8) * 2,
                       qbase + (size_t)r * C3 + c8 * 8);
        }
        CP_COMMIT();
        CP_WAIT(0);
    }
    __syncthreads();

    uint32_t aq[4][4];
    {
        const __half2 sc = __half2half2(__float2half(0.125f));
        #pragma unroll
        for (int kd = 0; kd < 4; kd++) {
            ldmatrix_x4(aq[kd], psb + (a_off + kd * 16) * 2);
            #pragma unroll
            for (int q = 0; q < 4; q++) {
                __half2 t = *(__half2*)&aq[kd][q];
                t = __hmul2(t, sc);
                aq[kd][q] = *(uint32_t*)&t;
            }
        }
    }
    __syncthreads();

    auto load_kv = [&](int st, int kt) {
        const __half* kb = kbase + (size_t)(kt * 64) * C3;
        const __half* vb = vbase + kt * 64;
        const uint32_t kss = smb + (uint32_t)(st * AKV_H) * 2;
        const uint32_t vss = smb + (uint32_t)((3 + st) * AKV_H) * 2;
        #pragma unroll
        for (int i = 0; i < 2; i++) {
            int chunk = tid + 256 * i;
            int r = chunk >> 3, c8 = chunk & 7;
            cp_async16(kss + (uint32_t)(r * ATC + c8 * 8) * 2,
                       kb + (size_t)r * C3 + c8 * 8);
            cp_async16(vss + (uint32_t)(r * ATC + c8 * 8) * 2,
                       vb + (size_t)r * SEQ + c8 * 8);
        }
    };

    float m0 = -1e30f, m1 = -1e30f, l0 = 0.0f, l1 = 0.0f;
    float o[8][4];
    #pragma unroll
    for (int nt = 0; nt < 8; nt++)
        #pragma unroll
        for (int q = 0; q < 4; q++) o[nt][q] = 0.0f;

    const int nkt = 2 * qt + 2;
    const int warp_min_row = row_base + wid * 16;
    const int r0 = warp_min_row + lr;
    const int r1 = r0 + 8;
    __half* Pw = Ps + (wid * 16) * ATC;

    load_kv(0, 0);
    CP_COMMIT();
    if (nkt > 1) load_kv(1, 1);
    CP_COMMIT();

    for (int kt = 0; kt < nkt; kt++) {
        CP_WAIT(1);
        __syncthreads();
        if (kt + 2 < nkt) load_kv((kt + 2) % 3, kt + 2);
        CP_COMMIT();

        const int st = kt % 3;
        const uint32_t kss = smb + (uint32_t)(st * AKV_H) * 2;
        const uint32_t vss = smb + (uint32_t)((3 + st) * AKV_H) * 2;

        // ---- S = (Q*scale) @ K^T ----
        float s[8][4];
        #pragma unroll
        for (int nt = 0; nt < 8; nt++)
            #pragma unroll
            for (int q = 0; q < 4; q++) s[nt][q] = 0.0f;

        #pragma unroll
        for (int kd = 0; kd < 4; kd++) {
            #pragma unroll
            for (int np = 0; np < 4; np++) {
                uint32_t bk[4];
                ldmatrix_x4(bk, kss + (b_off[np] + kd * 16) * 2);
                mma_f16(s[2 * np],     aq[kd], &bk[0]);
                mma_f16(s[2 * np + 1], aq[kd], &bk[2]);
            }
        }

        // ---- causal mask ----
        if (kt * 64 + 63 > warp_min_row) {
            #pragma unroll
            for (int nt = 0; nt < 8; nt++) {
                const int c0 = kt * 64 + nt * 8 + 2 * lq;
                if (c0 > r0)     s[nt][0] = -1e30f;
                if (c0 + 1 > r0) s[nt][1] = -1e30f;
                if (c0 > r1)     s[nt][2] = -1e30f;
                if (c0 + 1 > r1) s[nt][3] = -1e30f;
            }
        }

        // ---- online softmax ----
        float mx0 = -1e30f, mx1 = -1e30f;
        #pragma unroll
        for (int nt = 0; nt < 8; nt++) {
            mx0 = fmaxf(mx0, fmaxf(s[nt][0], s[nt][1]));
            mx1 = fmaxf(mx1, fmaxf(s[nt][2], s[nt][3]));
        }
        mx0 = fmaxf(mx0, __shfl_xor_sync(0xffffffffu, mx0, 1));
        mx0 = fmaxf(mx0, __shfl_xor_sync(0xffffffffu, mx0, 2));
        mx1 = fmaxf(mx1, __shfl_xor_sync(0xffffffffu, mx1, 1));
        mx1 = fmaxf(mx1, __shfl_xor_sync(0xffffffffu, mx1, 2));

        const float mn0 = fmaxf(m0, mx0);
        const float mn1 = fmaxf(m1, mx1);
        const float a0 = __expf(m0 - mn0);
        const float a1 = __expf(m1 - mn1);
        m0 = mn0; m1 = mn1;

        float sum0 = 0.0f, sum1 = 0.0f;
        #pragma unroll
        for (int nt = 0; nt < 8; nt++) {
            float p00 = __expf(s[nt][0] - mn0);
            float p01 = __expf(s[nt][1] - mn0);
            float p10 = __expf(s[nt][2] - mn1);
            float p11 = __expf(s[nt][3] - mn1);
            sum0 += p00 + p01;
            sum1 += p10 + p11;
            __half2 hp0 = __floats2half2_rn(p00, p01);
            __half2 hp1 = __floats2half2_rn(p10, p11);
            *(uint32_t*)(Pw + lr * ATC + nt * 8 + 2 * lq) = *(uint32_t*)&hp0;
            *(uint32_t*)(Pw + (lr + 8) * ATC + nt * 8 + 2 * lq) = *(uint32_t*)&hp1;
        }
        sum0 += __shfl_xor_sync(0xffffffffu, sum0, 1);
        sum0 += __shfl_xor_sync(0xffffffffu, sum0, 2);
        sum1 += __shfl_xor_sync(0xffffffffu, sum1, 1);
        sum1 += __shfl_xor_sync(0xffffffffu, sum1, 2);
        l0 = l0 * a0 + sum0;
        l1 = l1 * a1 + sum1;

        #pragma unroll
        for (int nt = 0; nt < 8; nt++) {
            o[nt][0] *= a0; o[nt][1] *= a0;
            o[nt][2] *= a1; o[nt][3] *= a1;
        }
        __syncwarp();

        // ---- O += P @ V ----
        #pragma unroll
        for (int kj = 0; kj < 4; kj++) {
            uint32_t ap[4];
            ldmatrix_x4(ap, psb + (a_off + kj * 16) * 2);
            #pragma unroll
            for (int np = 0; np < 4; np++) {
                uint32_t bv[4];
                ldmatrix_x4(bv, vss + (b_off[np] + kj * 16) * 2);
                mma_f16(o[2 * np],     ap, &bv[0]);
                mma_f16(o[2 * np + 1], ap, &bv[2]);
            }
        }
    }

    // ---- epilogue ----
    const float inv0 = 1.0f / l0;
    const float inv1 = 1.0f / l1;
    __half* y0 = y + (size_t)(b * SEQ + r0) * CDIM + h * HDIM;
    __half* y1 = y + (size_t)(b * SEQ + r1) * CDIM + h * HDIM;
    #pragma unroll
    for (int nt = 0; nt < 8; nt++) {
        const int c = nt * 8 + 2 * lq;
        __half2 h0 = __floats2half2_rn(o[nt][0] * inv0, o[nt][1] * inv0);
        __half2 h1 = __floats2half2_rn(o[nt][2] * inv1, o[nt][3] * inv1);
        *(uint32_t*)(y0 + c) = *(uint32_t*)&h0;
        *(uint32_t*)(y1 + c) = *(uint32_t*)&h1;
    }
}

// ---------------------------------------------------------------------------
extern "C" void kernel_launch(void* const* d_in, const int* in_sizes, int n_in,
                              void* d_out, int out_size)
{
    const float* x      = (const float*)d_in[0];
    const float* W_attn = (const float*)d_in[1];
    const float* b_attn = (const float*)d_in[2];
    const float* W_proj = (const float*)d_in[3];
    const float* b_proj = (const float*)d_in[4];
    float* out = (float*)d_out;

    __half *xh, *yh, *qkvh, *vt, *wat, *wpt;
    cudaGetSymbolAddress((void**)&xh, g_xh);
    cudaGetSymbolAddress((void**)&yh, g_yh);
    cudaGetSymbolAddress((void**)&qkvh, g_qkvh);
    cudaGetSymbolAddress((void**)&vt, g_vt);
    cudaGetSymbolAddress((void**)&wat, g_wat);
    cudaGetSymbolAddress((void**)&wpt, g_wpt);

    conv_h_kernel<<<(MTOT * CDIM) / 1024, 256>>>(x, xh, MTOT * CDIM);
    {
        dim3 blk(32, 8);
        dim3 ga(C3 / 32, CDIM / 32);
        convtrans_kernel<<<ga, blk>>>(W_attn, wat, CDIM, C3);
        dim3 gp(CDIM / 32, CDIM / 32);
        convtrans_kernel<<<gp, blk>>>(W_proj, wpt, CDIM, CDIM);
    }

    {
        cudaFuncSetAttribute(gemm_h_kernel<1>,
                             cudaFuncAttributeMaxDynamicSharedMemorySize,
                             GEMM_SMEM);
        dim3 grid(C3 / 128, MTOT / 128);
        gemm_h_kernel<1><<<grid, 256, GEMM_SMEM>>>(xh, wat, b_attn, nullptr,
                                                   qkvh, vt, CDIM, C3);
    }
    {
        cudaFuncSetAttribute(attn_mma_kernel,
                             cudaFuncAttributeMaxDynamicSharedMemorySize,
                             ATTN_SMEM);
        dim3 grid(SEQ / 128, BATCH * NHEAD);
        attn_mma_kernel<<<grid, 256, ATTN_SMEM>>>(qkvh, vt, yh);
    }
    {
        cudaFuncSetAttribute(gemm_h_kernel<0>,
                             cudaFuncAttributeMaxDynamicSharedMemorySize,
                             GEMM_SMEM);
        dim3 grid(CDIM / 128, MTOT / 128);
        gemm_h_kernel<0><<<grid, 256, GEMM_SMEM>>>(yh, wpt, b_proj, out,
                                                   nullptr, nullptr,
                                                   CDIM, CDIM);
    }
}

// round 8
// speedup vs baseline: 7.6262x; 1.0487x over previous
#include <cuda_runtime.h>
#include <cuda_fp16.h>
#include <cstdint>
#include <math.h>

#define BATCH 16
#define SEQ   1024
#define CDIM  768
#define NHEAD 12
#define HDIM  64
#define C3    (3*CDIM)
#define MTOT  (BATCH*SEQ)

// Scratch (allocation-free rule: __device__ globals)
__device__ __half g_xh[(size_t)MTOT * CDIM];
__device__ __half g_yh[(size_t)MTOT * CDIM];
__device__ __half g_qkvh[(size_t)MTOT * C3];
__device__ __half g_vt[(size_t)BATCH * NHEAD * HDIM * SEQ]; // v [b,h,d,t]
__device__ __half g_wat[(size_t)C3 * CDIM];
__device__ __half g_wpt[(size_t)CDIM * CDIM];

// ============================================================================
// Baseline-PTX helpers
// ============================================================================
__device__ __forceinline__ uint32_t smem_u32(const void* p) {
    uint32_t a;
    asm("{ .reg .u64 t; cvta.to.shared.u64 t, %1; cvt.u32.u64 %0, t; }"
        : "=r"(a) : "l"(p));
    return a;
}
__device__ __forceinline__ void cp_async16(uint32_t dst, const void* src) {
    asm volatile("cp.async.cg.shared.global [%0], [%1], 16;"
                 :: "r"(dst), "l"(src));
}
#define CP_COMMIT() asm volatile("cp.async.commit_group;" ::: "memory")
#define CP_WAIT(n)  asm volatile("cp.async.wait_group %0;" :: "n"(n) : "memory")

__device__ __forceinline__ void mma_f16(float* d, const uint32_t* a,
                                        const uint32_t* b) {
    asm volatile(
        "mma.sync.aligned.m16n8k16.row.col.f32.f16.f16.f32 "
        "{%0,%1,%2,%3}, {%4,%5,%6,%7}, {%8,%9}, {%0,%1,%2,%3};"
        : "+f"(d[0]), "+f"(d[1]), "+f"(d[2]), "+f"(d[3])
        : "r"(a[0]), "r"(a[1]), "r"(a[2]), "r"(a[3]),
          "r"(b[0]), "r"(b[1]));
}
__device__ __forceinline__ void ldmatrix_x4(uint32_t* r, uint32_t addr) {
    asm volatile("ldmatrix.sync.aligned.m8n8.x4.shared.b16 {%0,%1,%2,%3}, [%4];"
        : "=r"(r[0]), "=r"(r[1]), "=r"(r[2]), "=r"(r[3]) : "r"(addr));
}
__device__ __forceinline__ uint32_t ex2_f16x2(uint32_t x) {
    uint32_t r;
    asm("ex2.approx.f16x2 %0, %1;" : "=r"(r) : "r"(x));
    return r;
}

// ============================================================================
// Converts
// ============================================================================
__global__ void conv_h_kernel(const float* __restrict__ in,
                              __half* __restrict__ out, int n)
{
    int i = (blockIdx.x * 256 + threadIdx.x) * 4;
    if (i < n) {
        float4 v = *(const float4*)(in + i);
        __half2 h0 = __floats2half2_rn(v.x, v.y);
        __half2 h1 = __floats2half2_rn(v.z, v.w);
        uint2 u = make_uint2(*(uint32_t*)&h0, *(uint32_t*)&h1);
        *(uint2*)(out + i) = u;
    }
}

__global__ void convtrans_kernel(const float* __restrict__ in,
                                 __half* __restrict__ out, int R, int Ccols)
{
    __shared__ __half t[32][33];
    int c = blockIdx.x * 32 + threadIdx.x;
    int r = blockIdx.y * 32 + threadIdx.y;
    #pragma unroll
    for (int j = 0; j < 32; j += 8)
        t[threadIdx.y + j][threadIdx.x] = __float2half(in[(size_t)(r + j) * Ccols + c]);
    __syncthreads();
    int orow = blockIdx.x * 32 + threadIdx.y;
    int oc   = blockIdx.y * 32 + threadIdx.x;
    #pragma unroll
    for (int j = 0; j < 32; j += 8)
        out[(size_t)(orow + j) * R + oc] = t[threadIdx.x][threadIdx.y + j];
}

// ============================================================================
// fp16 mma GEMM, ldmatrix fragments, 3-stage cp.async (1 barrier / iter).
// (unchanged from R7 — control group)
// ============================================================================
#define GST 72
#define NST 3
#define STAGE_H (2 * 128 * GST)
#define GEMM_SMEM (NST * STAGE_H * 2)           // 110592 B
#define VTS 136

template<int OUT_MODE>
__global__ __launch_bounds__(256, 2)
void gemm_h_kernel(const __half* __restrict__ A, const __half* __restrict__ Bt,
                   const float* __restrict__ bias, float* __restrict__ Cf,
                   __half* __restrict__ Ch, __half* __restrict__ vt,
                   int K, int N)
{
    extern __shared__ __half smh[];

    const int tid  = threadIdx.x;
    const int wid  = tid >> 5;
    const int lane = tid & 31;
    const int lr = lane >> 2;
    const int lq = lane & 3;
    const int bm = blockIdx.y * 128;
    const int bn = blockIdx.x * 128;
    const int warp_m = (wid & 1) * 64;
    const int warp_n = (wid >> 1) * 32;

    const int l7 = lane & 7;
    const int gA_row = (lane >> 3) & 1;
    const int gA_k   = lane >> 4;
    uint32_t aoff[4];
    #pragma unroll
    for (int mi = 0; mi < 4; mi++)
        aoff[mi] = (uint32_t)((warp_m + mi * 16 + l7 + gA_row * 8) * GST
                              + gA_k * 8);
    const int gB_k = (lane >> 3) & 1;
    const int gB_n = lane >> 4;
    uint32_t boff[2];
    #pragma unroll
    for (int nj = 0; nj < 2; nj++)
        boff[nj] = (uint32_t)((warp_n + nj * 16 + l7 + gB_n * 8) * GST
                              + gB_k * 8);

    const uint32_t smb = smem_u32(smh);

    auto load_tile = [&](int st, int it) {
        const int koff = it * 64;
        const uint32_t asb = smb + (uint32_t)(st * STAGE_H) * 2;
        const uint32_t bsb = asb + (uint32_t)(128 * GST) * 2;
        #pragma unroll
        for (int i = 0; i < 4; ++i) {
            int chunk = tid + 256 * i;
            int r = chunk >> 3, c8 = chunk & 7;
            cp_async16(asb + (uint32_t)(r * GST + c8 * 8) * 2,
                       A + (size_t)(bm + r) * K + koff + c8 * 8);
            cp_async16(bsb + (uint32_t)(r * GST + c8 * 8) * 2,
                       Bt + (size_t)(bn + r) * K + koff + c8 * 8);
        }
    };

    float acc[4][4][4];
    #pragma unroll
    for (int mi = 0; mi < 4; mi++)
        #pragma unroll
        for (int ni = 0; ni < 4; ni++)
            #pragma unroll
            for (int q = 0; q < 4; q++) acc[mi][ni][q] = 0.0f;

    const int nk = K / 64;
    load_tile(0, 0);
    CP_COMMIT();
    load_tile(1, 1);
    CP_COMMIT();

    for (int it = 0; it < nk; ++it) {
        CP_WAIT(1);
        __syncthreads();
        if (it + 2 < nk) load_tile((it + 2) % NST, it + 2);
        CP_COMMIT();

        const int st = it % NST;
        const uint32_t asb = smb + (uint32_t)(st * STAGE_H) * 2;
        const uint32_t bsb = asb + (uint32_t)(128 * GST) * 2;

        #pragma unroll
        for (int ks = 0; ks < 4; ks++) {
            const int k0 = ks * 16;
            uint32_t af[4][4];
            #pragma unroll
            for (int mi = 0; mi < 4; mi++)
                ldmatrix_x4(af[mi], asb + (aoff[mi] + k0) * 2);
            uint32_t bf[2][4];
            #pragma unroll
            for (int nj = 0; nj < 2; nj++)
                ldmatrix_x4(bf[nj], bsb + (boff[nj] + k0) * 2);
            #pragma unroll
            for (int mi = 0; mi < 4; mi++)
                #pragma unroll
                for (int ni = 0; ni < 4; ni++)
                    mma_f16(acc[mi][ni], af[mi], &bf[ni >> 1][(ni & 1) * 2]);
        }
    }

    const int lc2 = lq * 2;
    const bool is_v = (OUT_MODE == 1) && (bn >= 2 * CDIM);

    if (is_v) {
        __syncthreads();
        __half* Vt = smh;
        #pragma unroll
        for (int ni = 0; ni < 4; ni++) {
            const int c = warp_n + ni * 8 + lc2;
            const float2 bv = *(const float2*)(bias + bn + c);
            #pragma unroll
            for (int mi = 0; mi < 4; mi++) {
                const int r = warp_m + mi * 16 + lr;
                Vt[(c    ) * VTS + r    ] = __float2half(acc[mi][ni][0] + bv.x);
                Vt[(c + 1) * VTS + r    ] = __float2half(acc[mi][ni][1] + bv.y);
                Vt[(c    ) * VTS + r + 8] = __float2half(acc[mi][ni][2] + bv.x);
                Vt[(c + 1) * VTS + r + 8] = __float2half(acc[mi][ni][3] + bv.y);
            }
        }
        __syncthreads();
        const int b = bm >> 10;
        const int t0 = bm & 1023;
        for (int i = tid; i < 128 * 16; i += 256) {
            const int c  = i >> 4;
            const int x8 = (i & 15) * 8;
            const int colv = bn - 2 * CDIM + c;
            const int h = colv >> 6, d = colv & 63;
            uint4 val = *(const uint4*)&Vt[c * VTS + x8];
            *(uint4*)(vt + ((size_t)(b * NHEAD + h) * HDIM + d) * SEQ + t0 + x8) = val;
        }
        return;
    }

    #pragma unroll
    for (int ni = 0; ni < 4; ni++) {
        const int col = bn + warp_n + ni * 8 + lc2;
        const float2 bv = *(const float2*)(bias + col);
        #pragma unroll
        for (int mi = 0; mi < 4; mi++) {
            const int row0 = bm + warp_m + mi * 16 + lr;
            float v00 = acc[mi][ni][0] + bv.x, v01 = acc[mi][ni][1] + bv.y;
            float v10 = acc[mi][ni][2] + bv.x, v11 = acc[mi][ni][3] + bv.y;
            if (OUT_MODE == 0) {
                *(float2*)(Cf + (size_t)row0 * N + col) = make_float2(v00, v01);
                *(float2*)(Cf + (size_t)(row0 + 8) * N + col) = make_float2(v10, v11);
            } else {
                __half2 h0 = __floats2half2_rn(v00, v01);
                __half2 h1 = __floats2half2_rn(v10, v11);
                *(uint32_t*)(Ch + (size_t)row0 * N + col) = *(uint32_t*)&h0;
                *(uint32_t*)(Ch + (size_t)(row0 + 8) * N + col) = *(uint32_t*)&h1;
            }
        }
    }
}

// ============================================================================
// Flash attention: fp16 mma, register-resident P (no smem round-trip),
// ex2.approx.f16x2 softmax, fully-masked-tile skip, 3-stage K/V pipeline.
// ============================================================================
#define ATC 72
#define AKV_H (64 * ATC)
#define ATTN_SMEM (6 * AKV_H * 2)    // 55296 B

__global__ __launch_bounds__(256, 2)
void attn_mma_kernel(const __half* __restrict__ qkv,
                     const __half* __restrict__ vt,
                     __half* __restrict__ y)
{
    extern __shared__ __half smh[];

    const int tid  = threadIdx.x;
    const int wid  = tid >> 5;
    const int lane = tid & 31;
    const int lr = lane >> 2;
    const int lq = lane & 3;
    const int qt = blockIdx.x;
    const int bh = blockIdx.y;
    const int b = bh / NHEAD;
    const int h = bh % NHEAD;
    const int row_base = qt * 128;

    const __half* qbase = qkv + ((size_t)(b * SEQ) + row_base) * C3 + h * HDIM;
    const __half* kbase = qkv + (size_t)(b * SEQ) * C3 + CDIM + h * HDIM;
    const __half* vbase = vt + (size_t)(b * NHEAD + h) * HDIM * SEQ;

    const int l7 = lane & 7;
    const uint32_t a_off = (uint32_t)((wid * 16 + l7 + ((lane >> 3) & 1) * 8) * ATC
                                      + (lane >> 4) * 8);
    uint32_t b_off[4];
    #pragma unroll
    for (int np = 0; np < 4; np++)
        b_off[np] = (uint32_t)((np * 16 + l7 + (lane >> 4) * 8) * ATC
                               + ((lane >> 3) & 1) * 8);

    const uint32_t smb = smem_u32(smh);

    // Stage Q tile [128][64] into the first two K-stage slots (reused after)
    {
        #pragma unroll
        for (int i = 0; i < 4; i++) {
            int chunk = tid + 256 * i;
            int r = chunk >> 3, c8 = chunk & 7;
            cp_async16(smb + (uint32_t)(r * ATC + c8 * 8) * 2,
                       qbase + (size_t)r * C3 + c8 * 8);
        }
        CP_COMMIT();
        CP_WAIT(0);
    }
    __syncthreads();

    uint32_t aq[4][4];
    {
        const __half2 sc = __half2half2(__float2half(0.125f));
        #pragma unroll
        for (int kd = 0; kd < 4; kd++) {
            ldmatrix_x4(aq[kd], smb + (a_off + kd * 16) * 2);
            #pragma unroll
            for (int q = 0; q < 4; q++) {
                __half2 t = *(__half2*)&aq[kd][q];
                t = __hmul2(t, sc);
                aq[kd][q] = *(uint32_t*)&t;
            }
        }
    }
    __syncthreads();   // Q reads done before K/V pipeline overwrites

    auto load_kv = [&](int st, int kt) {
        const __half* kb = kbase + (size_t)(kt * 64) * C3;
        const __half* vb = vbase + kt * 64;
        const uint32_t kss = smb + (uint32_t)(st * AKV_H) * 2;
        const uint32_t vss = smb + (uint32_t)((3 + st) * AKV_H) * 2;
        #pragma unroll
        for (int i = 0; i < 2; i++) {
            int chunk = tid + 256 * i;
            int r = chunk >> 3, c8 = chunk & 7;
            cp_async16(kss + (uint32_t)(r * ATC + c8 * 8) * 2,
                       kb + (size_t)r * C3 + c8 * 8);
            cp_async16(vss + (uint32_t)(r * ATC + c8 * 8) * 2,
                       vb + (size_t)r * SEQ + c8 * 8);
        }
    };

    float m0 = -1e30f, m1 = -1e30f, l0 = 0.0f, l1 = 0.0f;
    float o[8][4];
    #pragma unroll
    for (int nt = 0; nt < 8; nt++)
        #pragma unroll
        for (int q = 0; q < 4; q++) o[nt][q] = 0.0f;

    const int nkt = 2 * qt + 2;
    const int warp_min_row = row_base + wid * 16;
    const int r0 = warp_min_row + lr;
    const int r1 = r0 + 8;
    const float L2E = 1.44269504f;

    load_kv(0, 0);
    CP_COMMIT();
    load_kv(1, 1);
    CP_COMMIT();

    for (int kt = 0; kt < nkt; kt++) {
        CP_WAIT(1);
        __syncthreads();
        if (kt + 2 < nkt) load_kv((kt + 2) % 3, kt + 2);
        CP_COMMIT();

        // Fully-masked tile for this warp? (all keys > all rows)
        if (kt * 64 > warp_min_row + 15) continue;

        const int st = kt % 3;
        const uint32_t kss = smb + (uint32_t)(st * AKV_H) * 2;
        const uint32_t vss = smb + (uint32_t)((3 + st) * AKV_H) * 2;

        // ---- S = (Q*scale) @ K^T ----
        float s[8][4];
        #pragma unroll
        for (int nt = 0; nt < 8; nt++)
            #pragma unroll
            for (int q = 0; q < 4; q++) s[nt][q] = 0.0f;

        #pragma unroll
        for (int kd = 0; kd < 4; kd++) {
            #pragma unroll
            for (int np = 0; np < 4; np++) {
                uint32_t bk[4];
                ldmatrix_x4(bk, kss + (b_off[np] + kd * 16) * 2);
                mma_f16(s[2 * np],     aq[kd], &bk[0]);
                mma_f16(s[2 * np + 1], aq[kd], &bk[2]);
            }
        }

        // ---- causal mask (diagonal band) ----
        if (kt * 64 + 63 > warp_min_row) {
            #pragma unroll
            for (int nt = 0; nt < 8; nt++) {
                const int c0 = kt * 64 + nt * 8 + 2 * lq;
                if (c0 > r0)     s[nt][0] = -1e30f;
                if (c0 + 1 > r0) s[nt][1] = -1e30f;
                if (c0 > r1)     s[nt][2] = -1e30f;
                if (c0 + 1 > r1) s[nt][3] = -1e30f;
            }
        }

        // ---- online softmax (base-2, fp16 ex2) ----
        float mx0 = -1e30f, mx1 = -1e30f;
        #pragma unroll
        for (int nt = 0; nt < 8; nt++) {
            mx0 = fmaxf(mx0, fmaxf(s[nt][0], s[nt][1]));
            mx1 = fmaxf(mx1, fmaxf(s[nt][2], s[nt][3]));
        }
        mx0 = fmaxf(mx0, __shfl_xor_sync(0xffffffffu, mx0, 1));
        mx0 = fmaxf(mx0, __shfl_xor_sync(0xffffffffu, mx0, 2));
        mx1 = fmaxf(mx1, __shfl_xor_sync(0xffffffffu, mx1, 1));
        mx1 = fmaxf(mx1, __shfl_xor_sync(0xffffffffu, mx1, 2));

        const float mn0 = fmaxf(m0, mx0);
        const float mn1 = fmaxf(m1, mx1);
        const float a0 = __expf(m0 - mn0);
        const float a1 = __expf(m1 - mn1);
        m0 = mn0; m1 = mn1;

        // P fragments directly in registers (C-frag of S == A-frag of P)
        uint32_t ph[8][2];
        float sum0 = 0.0f, sum1 = 0.0f;
        #pragma unroll
        for (int nt = 0; nt < 8; nt++) {
            __half2 t0 = __floats2half2_rn((s[nt][0] - mn0) * L2E,
                                           (s[nt][1] - mn0) * L2E);
            __half2 t1 = __floats2half2_rn((s[nt][2] - mn1) * L2E,
                                           (s[nt][3] - mn1) * L2E);
            ph[nt][0] = ex2_f16x2(*(uint32_t*)&t0);
            ph[nt][1] = ex2_f16x2(*(uint32_t*)&t1);
            float2 f0 = __half22float2(*(__half2*)&ph[nt][0]);
            float2 f1 = __half22float2(*(__half2*)&ph[nt][1]);
            sum0 += f0.x + f0.y;
            sum1 += f1.x + f1.y;
        }
        sum0 += __shfl_xor_sync(0xffffffffu, sum0, 1);
        sum0 += __shfl_xor_sync(0xffffffffu, sum0, 2);
        sum1 += __shfl_xor_sync(0xffffffffu, sum1, 1);
        sum1 += __shfl_xor_sync(0xffffffffu, sum1, 2);
        l0 = l0 * a0 + sum0;
        l1 = l1 * a1 + sum1;

        #pragma unroll
        for (int nt = 0; nt < 8; nt++) {
            o[nt][0] *= a0; o[nt][1] *= a0;
            o[nt][2] *= a1; o[nt][3] *= a1;
        }

        // ---- O += P @ V (P fragments from registers) ----
        #pragma unroll
        for (int kj = 0; kj < 4; kj++) {
            uint32_t ap[4] = { ph[2*kj][0], ph[2*kj][1],
                               ph[2*kj+1][0], ph[2*kj+1][1] };
            #pragma unroll
            for (int np = 0; np < 4; np++) {
                uint32_t bv[4];
                ldmatrix_x4(bv, vss + (b_off[np] + kj * 16) * 2);
                mma_f16(o[2 * np],     ap, &bv[0]);
                mma_f16(o[2 * np + 1], ap, &bv[2]);
            }
        }
    }

    // ---- epilogue ----
    const float inv0 = 1.0f / l0;
    const float inv1 = 1.0f / l1;
    __half* y0 = y + (size_t)(b * SEQ + r0) * CDIM + h * HDIM;
    __half* y1 = y + (size_t)(b * SEQ + r1) * CDIM + h * HDIM;
    #pragma unroll
    for (int nt = 0; nt < 8; nt++) {
        const int c = nt * 8 + 2 * lq;
        __half2 h0 = __floats2half2_rn(o[nt][0] * inv0, o[nt][1] * inv0);
        __half2 h1 = __floats2half2_rn(o[nt][2] * inv1, o[nt][3] * inv1);
        *(uint32_t*)(y0 + c) = *(uint32_t*)&h0;
        *(uint32_t*)(y1 + c) = *(uint32_t*)&h1;
    }
}

// ---------------------------------------------------------------------------
extern "C" void kernel_launch(void* const* d_in, const int* in_sizes, int n_in,
                              void* d_out, int out_size)
{
    const float* x      = (const float*)d_in[0];
    const float* W_attn = (const float*)d_in[1];
    const float* b_attn = (const float*)d_in[2];
    const float* W_proj = (const float*)d_in[3];
    const float* b_proj = (const float*)d_in[4];
    float* out = (float*)d_out;

    __half *xh, *yh, *qkvh, *vt, *wat, *wpt;
    cudaGetSymbolAddress((void**)&xh, g_xh);
    cudaGetSymbolAddress((void**)&yh, g_yh);
    cudaGetSymbolAddress((void**)&qkvh, g_qkvh);
    cudaGetSymbolAddress((void**)&vt, g_vt);
    cudaGetSymbolAddress((void**)&wat, g_wat);
    cudaGetSymbolAddress((void**)&wpt, g_wpt);

    conv_h_kernel<<<(MTOT * CDIM) / 1024, 256>>>(x, xh, MTOT * CDIM);
    {
        dim3 blk(32, 8);
        dim3 ga(C3 / 32, CDIM / 32);
        convtrans_kernel<<<ga, blk>>>(W_attn, wat, CDIM, C3);
        dim3 gp(CDIM / 32, CDIM / 32);
        convtrans_kernel<<<gp, blk>>>(W_proj, wpt, CDIM, CDIM);
    }

    {
        cudaFuncSetAttribute(gemm_h_kernel<1>,
                             cudaFuncAttributeMaxDynamicSharedMemorySize,
                             GEMM_SMEM);
        dim3 grid(C3 / 128, MTOT / 128);
        gemm_h_kernel<1><<<grid, 256, GEMM_SMEM>>>(xh, wat, b_attn, nullptr,
                                                   qkvh, vt, CDIM, C3);
    }
    {
        cudaFuncSetAttribute(attn_mma_kernel,
                             cudaFuncAttributeMaxDynamicSharedMemorySize,
                             ATTN_SMEM);
        dim3 grid(SEQ / 128, BATCH * NHEAD);
        attn_mma_kernel<<<grid, 256, ATTN_SMEM>>>(qkvh, vt, yh);
    }
    {
        cudaFuncSetAttribute(gemm_h_kernel<0>,
                             cudaFuncAttributeMaxDynamicSharedMemorySize,
                             GEMM_SMEM);
        dim3 grid(CDIM / 128, MTOT / 128);
        gemm_h_kernel<0><<<grid, 256, GEMM_SMEM>>>(yh, wpt, b_proj, out,
                                                   nullptr, nullptr,
                                                   CDIM, CDIM);
    }
}